// round 9
// baseline (speedup 1.0000x reference)
#include <cuda_runtime.h>
#include <cuda_bf16.h>
#include <cstdint>

// ---------------- fixed problem dimensions ----------------------------------
#define NNODES 204800
#define NEDGES 409600
#define INCH   128
#define HID    256
#define NCOMP  8192
#define NGRAPH 4096
#define NPC    25
#define CPG    2
#define SDIM   64
#define MSET   8
#define KWC    512

// ---------------- scratch ----------------------------------------------------
__device__ float g_hsum[(size_t)NNODES * HID];
__device__ float g_t1  [(size_t)NNODES * HID];
__device__ float g_h   [(size_t)NNODES * HID];
__device__ float g_cm  [NCOMP * HID];
__device__ float g_tt  [NCOMP * KWC];
__device__ float g_pool[NGRAPH * SDIM];
__device__ float g_tfc [NGRAPH * 32];
__device__ float g_stats[64];

// transposed + hi/lo-split weights, bf16, [N][K] K-major
#define OFF_W0A  0
#define OFF_W0B  32768
#define OFF_WRA0 98304
#define OFF_WRB0 163840
#define OFF_WRA1 229376
#define OFF_WRB1 294912
#define OFF_WC   360448
#define WT_TOTAL 491520
__device__ __nv_bfloat16 g_wt_hi[WT_TOTAL];
__device__ __nv_bfloat16 g_wt_lo[WT_TOTAL];

// ---------------- helpers ------------------------------------------------------
__device__ __forceinline__ uint32_t smem_u32(const void* p) {
    uint32_t a;
    asm("{ .reg .u64 t; cvta.to.shared.u64 t, %1; cvt.u32.u64 %0, t; }" : "=r"(a) : "l"(p));
    return a;
}

#define LDSM_X4(r0, r1, r2, r3, addr)                                          \
    asm volatile("ldmatrix.sync.aligned.m8n8.x4.shared.b16 {%0,%1,%2,%3}, [%4];" \
                 : "=r"(r0), "=r"(r1), "=r"(r2), "=r"(r3) : "r"(addr))

#define MMA_BF16(d, a0, a1, a2, a3, b0, b1)                                    \
    asm volatile("mma.sync.aligned.m16n8k16.row.col.f32.bf16.bf16.f32 "        \
                 "{%0,%1,%2,%3}, {%4,%5,%6,%7}, {%8,%9}, {%0,%1,%2,%3};"       \
                 : "+f"((d)[0]), "+f"((d)[1]), "+f"((d)[2]), "+f"((d)[3])      \
                 : "r"(a0), "r"(a1), "r"(a2), "r"(a3), "r"(b0), "r"(b1))

#define CP_ASYNC_16(saddr, gptr)                                               \
    asm volatile("cp.async.cg.shared.global [%0], [%1], 16;"                   \
                 :: "r"(saddr), "l"(gptr))
#define CP_COMMIT() asm volatile("cp.async.commit_group;" ::: "memory")
#define CP_WAIT0()  asm volatile("cp.async.wait_group 0;" ::: "memory")

// ---------------- weight transpose + hi/lo split ------------------------------
__global__ void split_transpose(const float* __restrict__ w, __nv_bfloat16* __restrict__ hi,
                                __nv_bfloat16* __restrict__ lo, int K, int N) {
    int i = blockIdx.x * 256 + threadIdx.x;
    if (i >= K * N) return;
    int k = i / N, n = i % N;
    float v = w[i];
    __nv_bfloat16 h = __float2bfloat16(v);
    hi[(size_t)n * K + k] = h;
    lo[(size_t)n * K + k] = __float2bfloat16(v - __bfloat162float(h));
}

// ---------------- bf16x3 HMMA GEMM (KC=64, double buffer) -----------------------
// CTA tile 128x128, warp tile 64x32 (8 warps 2x4), K-chunk 64.
#define ROWB 144                 // 64 bf16 cols = 128B + 16B pad
#define A_ROWS 128
#define STAGE 73728              // Ahi|Alo|Bhi|Blo, each 128*144
#define AHI 0
#define ALO 18432
#define BHI 36864
#define BLO 55296
#define GEMM_SMEM (2 * STAGE)    // 147456

template <int ACT, bool DUAL>   // ACT: 0 none, 1 relu, 2 leaky(0.01)
__global__ void __launch_bounds__(256)
mma_gemm(const float* __restrict__ A, const __nv_bfloat16* __restrict__ BtHi,
         const __nv_bfloat16* __restrict__ BtLo, const float* __restrict__ bias,
         float* __restrict__ C, float* __restrict__ C2, int K, int N) {
    extern __shared__ char smem[];
    const uint32_t sb = smem_u32(smem);
    const int tid = threadIdx.x;
    const int lane = tid & 31, wid = tid >> 5;
    const int wm = wid >> 2, wn = wid & 3;
    const int m0 = blockIdx.y * 128, n0 = blockIdx.x * 128;

    const float* Ab = A + (size_t)m0 * K;
    const __nv_bfloat16* BHp = BtHi + (size_t)n0 * K;
    const __nv_bfloat16* BLp = BtLo + (size_t)n0 * K;

    float acc[4][4][4];
#pragma unroll
    for (int i = 0; i < 4; i++)
#pragma unroll
        for (int j = 0; j < 4; j++)
#pragma unroll
            for (int q = 0; q < 4; q++) acc[i][j][q] = 0.f;

    const uint32_t aOff = (uint32_t)(wm * 64 + (lane & 15)) * ROWB + (lane >> 4) * 16;
    const uint32_t bOff = (uint32_t)(wn * 32 + (lane & 7) + (lane >> 4) * 8) * ROWB +
                          ((lane >> 3) & 1) * 16;

    // fill coordinates
    const int arow = tid >> 4, ac4 = tid & 15;  // A: 8 iters of (row += 16), col=ac4*4
    const int brow = tid >> 3, bc8 = tid & 7;   // B: 4 iters of (row += 32), col=bc8*8 bf16

    auto loadA = [&](int k0, float4* av) {
#pragma unroll
        for (int i = 0; i < 8; i++)
            av[i] = *(const float4*)(Ab + (size_t)(arow + i * 16) * K + k0 + ac4 * 4);
    };
    auto storeA = [&](int buf, const float4* av) {
        char* sd = smem + buf * STAGE;
#pragma unroll
        for (int i = 0; i < 8; i++) {
            float4 v = av[i];
            __nv_bfloat16 h0 = __float2bfloat16(v.x), h1 = __float2bfloat16(v.y);
            __nv_bfloat16 h2 = __float2bfloat16(v.z), h3 = __float2bfloat16(v.w);
            __nv_bfloat16 l0 = __float2bfloat16(v.x - __bfloat162float(h0));
            __nv_bfloat16 l1 = __float2bfloat16(v.y - __bfloat162float(h1));
            __nv_bfloat16 l2 = __float2bfloat16(v.z - __bfloat162float(h2));
            __nv_bfloat16 l3 = __float2bfloat16(v.w - __bfloat162float(h3));
            union { __nv_bfloat162 b[2]; uint2 u; } uh, ul;
            uh.b[0] = __nv_bfloat162(h0, h1); uh.b[1] = __nv_bfloat162(h2, h3);
            ul.b[0] = __nv_bfloat162(l0, l1); ul.b[1] = __nv_bfloat162(l2, l3);
            int off = (arow + i * 16) * ROWB + ac4 * 8;
            *(uint2*)(sd + AHI + off) = uh.u;
            *(uint2*)(sd + ALO + off) = ul.u;
        }
    };
    auto asyncB = [&](int buf, int k0) {
        uint32_t sd = sb + buf * STAGE;
#pragma unroll
        for (int i = 0; i < 4; i++) {
            int row = brow + i * 32;
            uint32_t so = row * ROWB + bc8 * 16;
            CP_ASYNC_16(sd + BHI + so, BHp + (size_t)row * K + k0 + bc8 * 8);
            CP_ASYNC_16(sd + BLO + so, BLp + (size_t)row * K + k0 + bc8 * 8);
        }
    };

    auto compute = [&](int buf) {
        uint32_t sa = sb + buf * STAGE;
#pragma unroll
        for (int k16 = 0; k16 < 4; k16++) {
            uint32_t kadd = k16 * 32;
            uint32_t bh[8], bl[8];
#pragma unroll
            for (int p = 0; p < 2; p++) {
                LDSM_X4(bh[p * 4 + 0], bh[p * 4 + 1], bh[p * 4 + 2], bh[p * 4 + 3],
                        sa + BHI + bOff + p * (16 * ROWB) + kadd);
                LDSM_X4(bl[p * 4 + 0], bl[p * 4 + 1], bl[p * 4 + 2], bl[p * 4 + 3],
                        sa + BLO + bOff + p * (16 * ROWB) + kadd);
            }
#pragma unroll
            for (int mi = 0; mi < 4; mi++) {
                uint32_t ah0, ah1, ah2, ah3, al0, al1, al2, al3;
                LDSM_X4(ah0, ah1, ah2, ah3, sa + AHI + aOff + mi * (16 * ROWB) + kadd);
                LDSM_X4(al0, al1, al2, al3, sa + ALO + aOff + mi * (16 * ROWB) + kadd);
#pragma unroll
                for (int ni = 0; ni < 4; ni++) {
                    MMA_BF16(acc[mi][ni], ah0, ah1, ah2, ah3, bh[ni * 2], bh[ni * 2 + 1]);
                    MMA_BF16(acc[mi][ni], ah0, ah1, ah2, ah3, bl[ni * 2], bl[ni * 2 + 1]);
                    MMA_BF16(acc[mi][ni], al0, al1, al2, al3, bh[ni * 2], bh[ni * 2 + 1]);
                }
            }
        }
    };

    const int nchunk = K / 64;
    float4 av[8];

    loadA(0, av);
    asyncB(0, 0); CP_COMMIT();
    storeA(0, av);
    CP_WAIT0();
    __syncthreads();

    for (int c = 0; c < nchunk; c++) {
        if (c + 1 < nchunk) {
            loadA((c + 1) * 64, av);
            asyncB((c + 1) & 1, (c + 1) * 64); CP_COMMIT();
        }
        compute(c & 1);
        if (c + 1 < nchunk) {
            CP_WAIT0();
            storeA((c + 1) & 1, av);
        }
        __syncthreads();
    }

    // ---- epilogue ----
#pragma unroll
    for (int ni = 0; ni < 4; ni++) {
        int col = n0 + wn * 32 + ni * 8 + (lane & 3) * 2;
        float b0 = 0.f, b1 = 0.f;
        if (bias) { b0 = __ldg(bias + col); b1 = __ldg(bias + col + 1); }
#pragma unroll
        for (int mi = 0; mi < 4; mi++) {
            int row = m0 + wm * 64 + mi * 16 + (lane >> 2);
            float v0 = acc[mi][ni][0] + b0, v1 = acc[mi][ni][1] + b1;
            float v2 = acc[mi][ni][2] + b0, v3 = acc[mi][ni][3] + b1;
            if (ACT == 1) {
                v0 = fmaxf(v0, 0.f); v1 = fmaxf(v1, 0.f);
                v2 = fmaxf(v2, 0.f); v3 = fmaxf(v3, 0.f);
            } else if (ACT == 2) {
                v0 = v0 > 0.f ? v0 : 0.01f * v0;
                v1 = v1 > 0.f ? v1 : 0.01f * v1;
                v2 = v2 > 0.f ? v2 : 0.01f * v2;
                v3 = v3 > 0.f ? v3 : 0.01f * v3;
            }
            *(float2*)(C + (size_t)row * N + col) = make_float2(v0, v1);
            *(float2*)(C + (size_t)(row + 8) * N + col) = make_float2(v2, v3);
            if (DUAL) {
                *(float2*)(C2 + (size_t)row * N + col) = make_float2(v0, v1);
                *(float2*)(C2 + (size_t)(row + 8) * N + col) = make_float2(v2, v3);
            }
        }
    }
}

// ---------------- elementwise -------------------------------------------------
__global__ void copy_f4(const float4* __restrict__ src, float4* __restrict__ dst, int n) {
    int i = blockIdx.x * blockDim.x + threadIdx.x;
    if (i < n) dst[i] = src[i];
}

// ---------------- edge scatter --------------------------------------------------
__device__ __forceinline__ void red_add_v4(float* addr, float4 v) {
    asm volatile("red.global.add.v4.f32 [%0], {%1,%2,%3,%4};"
                 :: "l"(addr), "f"(v.x), "f"(v.y), "f"(v.z), "f"(v.w) : "memory");
}
template <int CH>
__global__ void scatter_kernel(const float* __restrict__ xin,
                               const int* __restrict__ src,
                               const int* __restrict__ dst) {
    int e = blockIdx.x * 8 + (threadIdx.x >> 5);
    int lane = threadIdx.x & 31;
    if (e >= NEDGES) return;
    int s = src[e], d = dst[e];
    const float* xs = xin + (size_t)s * CH;
    float* od = g_hsum + (size_t)d * CH;
#pragma unroll
    for (int j = 0; j < CH / 128; j++) {
        float4 v = *(const float4*)(xs + j * 128 + lane * 4);
        red_add_v4(od + j * 128 + lane * 4, v);
    }
}

// ---------------- pooling / head ------------------------------------------------
__global__ void pool_kernel() {
    int c = blockIdx.x, d = threadIdx.x;
    const float* p = g_h + (size_t)c * NPC * HID + d;
    float s = 0.f;
#pragma unroll
    for (int j = 0; j < NPC; j++) s += p[j * HID];
    g_cm[c * HID + d] = s * (1.0f / NPC);
}
__global__ void setpool_kernel() {
    int i = blockIdx.x * blockDim.x + threadIdx.x;
    int b = i >> 6, s = i & 63;
    float acc = 0.f;
#pragma unroll
    for (int c = 0; c < CPG; c++) {
        const float* t = g_tt + (size_t)(b * CPG + c) * KWC + s;
        float mx = -3.4e38f;
#pragma unroll
        for (int m = 0; m < MSET; m++) mx = fmaxf(mx, t[m * SDIM]);
        acc += mx;
    }
    g_pool[i] = acc;
}
__global__ void fc1_kernel(const float* __restrict__ w, const float* __restrict__ b) {
    __shared__ float sw[64 * 32];
    __shared__ float sb[32];
    int tid = threadIdx.x;
    for (int i = tid; i < 64 * 32; i += 256) sw[i] = w[i];
    if (tid < 32) sb[tid] = b[tid];
    __syncthreads();
    int r = blockIdx.x * 256 + tid;
    float acc[32];
#pragma unroll
    for (int o = 0; o < 32; o++) acc[o] = sb[o];
    const float* pr = g_pool + (size_t)r * 64;
    for (int d = 0; d < 64; d++) {
        float p = pr[d];
#pragma unroll
        for (int o = 0; o < 32; o++) acc[o] += p * sw[d * 32 + o];
    }
#pragma unroll
    for (int o = 0; o < 32; o++) g_tfc[r * 32 + o] = acc[o];
}
__global__ void stats_kernel() {
    __shared__ float ss[1024], sq[1024];
    int t = threadIdx.x;
    int col = t & 31, g = t >> 5;
    float s = 0.f, q = 0.f;
    for (int r = g; r < NGRAPH; r += 32) {
        float v = g_tfc[r * 32 + col];
        s += v; q += v * v;
    }
    ss[t] = s; sq[t] = q;
    __syncthreads();
    if (t < 32) {
        float S = 0.f, Q = 0.f;
#pragma unroll
        for (int gg = 0; gg < 32; gg++) { S += ss[gg * 32 + t]; Q += sq[gg * 32 + t]; }
        g_stats[t] = S; g_stats[32 + t] = Q;
    }
}
__global__ void fc2_kernel(const float* __restrict__ bng, const float* __restrict__ bnb,
                           const float* __restrict__ w2, const float* __restrict__ b2,
                           float* __restrict__ out) {
    int r = blockIdx.x * 256 + threadIdx.x;
    const float invB = 1.0f / NGRAPH;
    float l0 = b2[0], l1 = b2[1];
#pragma unroll
    for (int o = 0; o < 32; o++) {
        float mu  = g_stats[o] * invB;
        float var = g_stats[32 + o] * invB - mu * mu;
        float v = (g_tfc[r * 32 + o] - mu) * rsqrtf(var + 1e-5f) * bng[o] + bnb[o];
        v = v > 0.f ? v : 0.01f * v;
        l0 += v * w2[o * 2 + 0];
        l1 += v * w2[o * 2 + 1];
    }
    float m = fmaxf(l0, l1);
    float lse = m + logf(expf(l0 - m) + expf(l1 - m));
    out[r * 2 + 0] = l0 - lse;
    out[r * 2 + 1] = l1 - lse;
}

// ---------------- host launcher --------------------------------------------------
extern "C" void kernel_launch(void* const* d_in, const int* in_sizes, int n_in,
                              void* d_out, int out_size) {
    const float* x    = (const float*)d_in[0];
    const float* w0a  = (const float*)d_in[1];
    const float* b0a  = (const float*)d_in[2];
    const float* w0b  = (const float*)d_in[3];
    const float* b0b  = (const float*)d_in[4];
    const float* wra  = (const float*)d_in[5];
    const float* bra  = (const float*)d_in[6];
    const float* wrb  = (const float*)d_in[7];
    const float* brb  = (const float*)d_in[8];
    const float* Wc   = (const float*)d_in[9];
    const float* fc1w = (const float*)d_in[10];
    const float* fc1b = (const float*)d_in[11];
    const float* bng  = (const float*)d_in[12];
    const float* bnb  = (const float*)d_in[13];
    const float* fc2w = (const float*)d_in[14];
    const float* fc2b = (const float*)d_in[15];
    const int*   ei   = (const int*)d_in[16];
    const int* src = ei;
    const int* dst = ei + NEDGES;
    float* out = (float*)d_out;

    void* p;
    cudaGetSymbolAddress(&p, g_hsum); float* hsum = (float*)p;
    cudaGetSymbolAddress(&p, g_t1);   float* t1   = (float*)p;
    cudaGetSymbolAddress(&p, g_h);    float* h    = (float*)p;
    cudaGetSymbolAddress(&p, g_cm);   float* cm   = (float*)p;
    cudaGetSymbolAddress(&p, g_tt);   float* tt   = (float*)p;
    cudaGetSymbolAddress(&p, g_wt_hi); __nv_bfloat16* wh = (__nv_bfloat16*)p;
    cudaGetSymbolAddress(&p, g_wt_lo); __nv_bfloat16* wl = (__nv_bfloat16*)p;

    cudaFuncSetAttribute((const void*)mma_gemm<0, false>, cudaFuncAttributeMaxDynamicSharedMemorySize, GEMM_SMEM);
    cudaFuncSetAttribute((const void*)mma_gemm<1, false>, cudaFuncAttributeMaxDynamicSharedMemorySize, GEMM_SMEM);
    cudaFuncSetAttribute((const void*)mma_gemm<1, true>,  cudaFuncAttributeMaxDynamicSharedMemorySize, GEMM_SMEM);
    cudaFuncSetAttribute((const void*)mma_gemm<2, false>, cudaFuncAttributeMaxDynamicSharedMemorySize, GEMM_SMEM);

    // ---- weight transpose + split (tiny) ----
    split_transpose<<<(INCH * HID + 255) / 256, 256>>>(w0a, wh + OFF_W0A, wl + OFF_W0A, INCH, HID);
    split_transpose<<<(HID * HID + 255) / 256, 256>>>(w0b, wh + OFF_W0B, wl + OFF_W0B, HID, HID);
    split_transpose<<<(HID * HID + 255) / 256, 256>>>(wra,             wh + OFF_WRA0, wl + OFF_WRA0, HID, HID);
    split_transpose<<<(HID * HID + 255) / 256, 256>>>(wra + HID * HID, wh + OFF_WRA1, wl + OFF_WRA1, HID, HID);
    split_transpose<<<(HID * HID + 255) / 256, 256>>>(wrb,             wh + OFF_WRB0, wl + OFF_WRB0, HID, HID);
    split_transpose<<<(HID * HID + 255) / 256, 256>>>(wrb + HID * HID, wh + OFF_WRB1, wl + OFF_WRB1, HID, HID);
    split_transpose<<<(HID * KWC + 255) / 256, 256>>>(Wc, wh + OFF_WC, wl + OFF_WC, HID, KWC);

    dim3 gBig(HID / 128, NNODES / 128);   // (2, 1600)

    // ---- conv0 (K=128) ----
    copy_f4<<<(NNODES * INCH / 4) / 256, 256>>>((const float4*)x, (float4*)hsum, NNODES * INCH / 4);
    scatter_kernel<INCH><<<NEDGES / 8, 256>>>(x, src, dst);
    mma_gemm<1, false><<<gBig, 256, GEMM_SMEM>>>(hsum, wh + OFF_W0A, wl + OFF_W0A, b0a, t1, nullptr, INCH, HID);
    mma_gemm<1, true><<<gBig, 256, GEMM_SMEM>>>(t1, wh + OFF_W0B, wl + OFF_W0B, b0b, h, hsum, HID, HID);

    // ---- conv1 ----
    scatter_kernel<HID><<<NEDGES / 8, 256>>>(h, src, dst);
    mma_gemm<1, false><<<gBig, 256, GEMM_SMEM>>>(hsum, wh + OFF_WRA0, wl + OFF_WRA0, bra, t1, nullptr, HID, HID);
    mma_gemm<1, true><<<gBig, 256, GEMM_SMEM>>>(t1, wh + OFF_WRB0, wl + OFF_WRB0, brb, h, hsum, HID, HID);

    // ---- conv2 (no trailing relu) ----
    scatter_kernel<HID><<<NEDGES / 8, 256>>>(h, src, dst);
    mma_gemm<1, false><<<gBig, 256, GEMM_SMEM>>>(hsum, wh + OFF_WRA1, wl + OFF_WRA1, bra + HID, t1, nullptr, HID, HID);
    mma_gemm<0, false><<<gBig, 256, GEMM_SMEM>>>(t1, wh + OFF_WRB1, wl + OFF_WRB1, brb + HID, h, nullptr, HID, HID);

    // ---- pooling ----
    pool_kernel<<<NCOMP, HID>>>();

    // ---- set-rep GEMM: leaky(cm @ Wc), M=8192, N=512, K=256 ----
    {
        dim3 grid(KWC / 128, NCOMP / 128);
        mma_gemm<2, false><<<grid, 256, GEMM_SMEM>>>(cm, wh + OFF_WC, wl + OFF_WC, nullptr, tt, nullptr, HID, KWC);
    }
    setpool_kernel<<<(NGRAPH * SDIM) / 256, 256>>>();

    // ---- head ----
    fc1_kernel<<<NGRAPH / 256, 256>>>(fc1w, fc1b);
    stats_kernel<<<1, 1024>>>();
    fc2_kernel<<<NGRAPH / 256, 256>>>(bng, bnb, fc2w, fc2b, out);
}

// round 10
// speedup vs baseline: 1.0927x; 1.0927x over previous
#include <cuda_runtime.h>
#include <cuda_bf16.h>
#include <cstdint>

// ---------------- fixed problem dimensions ----------------------------------
#define NNODES 204800
#define NEDGES 409600
#define INCH   128
#define HID    256
#define NCOMP  8192
#define NGRAPH 4096
#define NPC    25
#define CPG    2
#define SDIM   64
#define MSET   8
#define KWC    512

// ---------------- scratch ----------------------------------------------------
__device__ float g_hsum[(size_t)NNODES * HID];
__device__ float g_t1  [(size_t)NNODES * HID];
__device__ float g_h   [(size_t)NNODES * HID];
__device__ float g_cm  [NCOMP * HID];
__device__ float g_tt  [NCOMP * KWC];
__device__ float g_pool[NGRAPH * SDIM];
__device__ float g_tfc [NGRAPH * 32];
__device__ float g_stats[64];

// transposed + hi/lo-split weights, bf16, [N][K] K-major
#define OFF_W0A  0
#define OFF_W0B  32768
#define OFF_WRA0 98304
#define OFF_WRB0 163840
#define OFF_WRA1 229376
#define OFF_WRB1 294912
#define OFF_WC   360448
#define WT_TOTAL 491520
__device__ __nv_bfloat16 g_wt_hi[WT_TOTAL];
__device__ __nv_bfloat16 g_wt_lo[WT_TOTAL];

// ---------------- helpers ------------------------------------------------------
__device__ __forceinline__ uint32_t smem_u32(const void* p) {
    uint32_t a;
    asm("{ .reg .u64 t; cvta.to.shared.u64 t, %1; cvt.u32.u64 %0, t; }" : "=r"(a) : "l"(p));
    return a;
}

#define LDSM_X4(r0, r1, r2, r3, addr)                                          \
    asm volatile("ldmatrix.sync.aligned.m8n8.x4.shared.b16 {%0,%1,%2,%3}, [%4];" \
                 : "=r"(r0), "=r"(r1), "=r"(r2), "=r"(r3) : "r"(addr))

#define MMA_BF16(d, a0, a1, a2, a3, b0, b1)                                    \
    asm volatile("mma.sync.aligned.m16n8k16.row.col.f32.bf16.bf16.f32 "        \
                 "{%0,%1,%2,%3}, {%4,%5,%6,%7}, {%8,%9}, {%0,%1,%2,%3};"       \
                 : "+f"((d)[0]), "+f"((d)[1]), "+f"((d)[2]), "+f"((d)[3])      \
                 : "r"(a0), "r"(a1), "r"(a2), "r"(a3), "r"(b0), "r"(b1))

#define CP_ASYNC_16(saddr, gptr)                                               \
    asm volatile("cp.async.cg.shared.global [%0], [%1], 16;"                   \
                 :: "r"(saddr), "l"(gptr))
#define CP_COMMIT() asm volatile("cp.async.commit_group;" ::: "memory")
#define CP_WAIT0()  asm volatile("cp.async.wait_group 0;" ::: "memory")

// ---------------- weight transpose + hi/lo split ------------------------------
__global__ void split_transpose(const float* __restrict__ w, __nv_bfloat16* __restrict__ hi,
                                __nv_bfloat16* __restrict__ lo, int K, int N) {
    int i = blockIdx.x * 256 + threadIdx.x;
    if (i >= K * N) return;
    int k = i / N, n = i % N;
    float v = w[i];
    __nv_bfloat16 h = __float2bfloat16(v);
    hi[(size_t)n * K + k] = h;
    lo[(size_t)n * K + k] = __float2bfloat16(v - __bfloat162float(h));
}

// ---------------- bf16x3 HMMA GEMM ---------------------------------------------
// CTA tile 64(M) x 128(N), 128 threads = 4 warps of 64x32, K-chunk 32, 2 stages.
// Small CTA -> 3 CTAs/SM (12 warps) at natural register count (no cap, no spill).
#define NTHR 128
#define ROWB 80
#define A_BYTES 5120            // 64 rows * 80B
#define B_BYTES 10240           // 128 rows * 80B
#define AHI 0
#define ALO 5120
#define BHI 10240
#define BLO 20480
#define STAGE 30720
#define GEMM_SMEM (2 * STAGE)   // 61440

template <int ACT, bool DUAL>   // ACT: 0 none, 1 relu, 2 leaky(0.01)
__global__ void __launch_bounds__(NTHR)
mma_gemm(const float* __restrict__ A, const __nv_bfloat16* __restrict__ BtHi,
         const __nv_bfloat16* __restrict__ BtLo, const float* __restrict__ bias,
         float* __restrict__ C, float* __restrict__ C2, int K, int N) {
    extern __shared__ char smem[];
    const uint32_t sb = smem_u32(smem);
    const int tid = threadIdx.x;
    const int lane = tid & 31, wid = tid >> 5;   // wid 0..3
    const int wn = wid;                          // warp column; wm = 0
    const int m0 = blockIdx.y * 64, n0 = blockIdx.x * 128;

    const float* Ab = A + (size_t)m0 * K;
    const __nv_bfloat16* BHp = BtHi + (size_t)n0 * K;
    const __nv_bfloat16* BLp = BtLo + (size_t)n0 * K;

    float acc[4][4][4];
#pragma unroll
    for (int i = 0; i < 4; i++)
#pragma unroll
        for (int j = 0; j < 4; j++)
#pragma unroll
            for (int q = 0; q < 4; q++) acc[i][j][q] = 0.f;

    const uint32_t aOff = (uint32_t)(lane & 15) * ROWB + (lane >> 4) * 16;
    const uint32_t bOff = (uint32_t)(wn * 32 + (lane & 7) + (lane >> 4) * 8) * ROWB +
                          ((lane >> 3) & 1) * 16;

    // fill coordinates (128 threads)
    const int arow = tid >> 3, ac4 = tid & 7;   // A: 4 iters (row += 16), 64 rows total
    const int brow = tid >> 2, bc8 = tid & 3;   // B: 4 iters (row += 32), 128 rows total

    auto loadA = [&](int k0, float4* av) {
#pragma unroll
        for (int i = 0; i < 4; i++)
            av[i] = *(const float4*)(Ab + (size_t)(arow + i * 16) * K + k0 + ac4 * 4);
    };
    auto storeA = [&](int buf, const float4* av) {
        char* sd = smem + buf * STAGE;
#pragma unroll
        for (int i = 0; i < 4; i++) {
            float4 v = av[i];
            __nv_bfloat16 h0 = __float2bfloat16(v.x), h1 = __float2bfloat16(v.y);
            __nv_bfloat16 h2 = __float2bfloat16(v.z), h3 = __float2bfloat16(v.w);
            __nv_bfloat16 l0 = __float2bfloat16(v.x - __bfloat162float(h0));
            __nv_bfloat16 l1 = __float2bfloat16(v.y - __bfloat162float(h1));
            __nv_bfloat16 l2 = __float2bfloat16(v.z - __bfloat162float(h2));
            __nv_bfloat16 l3 = __float2bfloat16(v.w - __bfloat162float(h3));
            union { __nv_bfloat162 b[2]; uint2 u; } uh, ul;
            uh.b[0] = __nv_bfloat162(h0, h1); uh.b[1] = __nv_bfloat162(h2, h3);
            ul.b[0] = __nv_bfloat162(l0, l1); ul.b[1] = __nv_bfloat162(l2, l3);
            int off = (arow + i * 16) * ROWB + ac4 * 8;
            *(uint2*)(sd + AHI + off) = uh.u;
            *(uint2*)(sd + ALO + off) = ul.u;
        }
    };
    auto asyncB = [&](int buf, int k0) {
        uint32_t sd = sb + buf * STAGE;
#pragma unroll
        for (int i = 0; i < 4; i++) {
            int row = brow + i * 32;
            uint32_t so = row * ROWB + bc8 * 16;
            CP_ASYNC_16(sd + BHI + so, BHp + (size_t)row * K + k0 + bc8 * 8);
            CP_ASYNC_16(sd + BLO + so, BLp + (size_t)row * K + k0 + bc8 * 8);
        }
    };

    auto compute = [&](int buf) {
        uint32_t sa = sb + buf * STAGE;
#pragma unroll
        for (int k16 = 0; k16 < 2; k16++) {
            uint32_t kadd = k16 * 32;
            uint32_t bh[8], bl[8];
#pragma unroll
            for (int p = 0; p < 2; p++) {
                LDSM_X4(bh[p * 4 + 0], bh[p * 4 + 1], bh[p * 4 + 2], bh[p * 4 + 3],
                        sa + BHI + bOff + p * (16 * ROWB) + kadd);
                LDSM_X4(bl[p * 4 + 0], bl[p * 4 + 1], bl[p * 4 + 2], bl[p * 4 + 3],
                        sa + BLO + bOff + p * (16 * ROWB) + kadd);
            }
#pragma unroll
            for (int mi = 0; mi < 4; mi++) {
                uint32_t ah0, ah1, ah2, ah3, al0, al1, al2, al3;
                LDSM_X4(ah0, ah1, ah2, ah3, sa + AHI + aOff + mi * (16 * ROWB) + kadd);
                LDSM_X4(al0, al1, al2, al3, sa + ALO + aOff + mi * (16 * ROWB) + kadd);
#pragma unroll
                for (int ni = 0; ni < 4; ni++) {
                    MMA_BF16(acc[mi][ni], ah0, ah1, ah2, ah3, bh[ni * 2], bh[ni * 2 + 1]);
                    MMA_BF16(acc[mi][ni], ah0, ah1, ah2, ah3, bl[ni * 2], bl[ni * 2 + 1]);
                    MMA_BF16(acc[mi][ni], al0, al1, al2, al3, bh[ni * 2], bh[ni * 2 + 1]);
                }
            }
        }
    };

    const int nchunk = K / 32;
    float4 av[4];

    loadA(0, av);
    asyncB(0, 0); CP_COMMIT();
    storeA(0, av);
    CP_WAIT0();
    __syncthreads();

    for (int c = 0; c < nchunk; c++) {
        if (c + 1 < nchunk) {
            loadA((c + 1) * 32, av);
            asyncB((c + 1) & 1, (c + 1) * 32); CP_COMMIT();
        }
        compute(c & 1);
        if (c + 1 < nchunk) {
            CP_WAIT0();
            storeA((c + 1) & 1, av);
        }
        __syncthreads();
    }

    // ---- epilogue ----
#pragma unroll
    for (int ni = 0; ni < 4; ni++) {
        int col = n0 + wn * 32 + ni * 8 + (lane & 3) * 2;
        float b0 = 0.f, b1 = 0.f;
        if (bias) { b0 = __ldg(bias + col); b1 = __ldg(bias + col + 1); }
#pragma unroll
        for (int mi = 0; mi < 4; mi++) {
            int row = m0 + mi * 16 + (lane >> 2);
            float v0 = acc[mi][ni][0] + b0, v1 = acc[mi][ni][1] + b1;
            float v2 = acc[mi][ni][2] + b0, v3 = acc[mi][ni][3] + b1;
            if (ACT == 1) {
                v0 = fmaxf(v0, 0.f); v1 = fmaxf(v1, 0.f);
                v2 = fmaxf(v2, 0.f); v3 = fmaxf(v3, 0.f);
            } else if (ACT == 2) {
                v0 = v0 > 0.f ? v0 : 0.01f * v0;
                v1 = v1 > 0.f ? v1 : 0.01f * v1;
                v2 = v2 > 0.f ? v2 : 0.01f * v2;
                v3 = v3 > 0.f ? v3 : 0.01f * v3;
            }
            *(float2*)(C + (size_t)row * N + col) = make_float2(v0, v1);
            *(float2*)(C + (size_t)(row + 8) * N + col) = make_float2(v2, v3);
            if (DUAL) {
                *(float2*)(C2 + (size_t)row * N + col) = make_float2(v0, v1);
                *(float2*)(C2 + (size_t)(row + 8) * N + col) = make_float2(v2, v3);
            }
        }
    }
}

// ---------------- elementwise -------------------------------------------------
__global__ void copy_f4(const float4* __restrict__ src, float4* __restrict__ dst, int n) {
    int i = blockIdx.x * blockDim.x + threadIdx.x;
    if (i < n) dst[i] = src[i];
}

// ---------------- edge scatter --------------------------------------------------
__device__ __forceinline__ void red_add_v4(float* addr, float4 v) {
    asm volatile("red.global.add.v4.f32 [%0], {%1,%2,%3,%4};"
                 :: "l"(addr), "f"(v.x), "f"(v.y), "f"(v.z), "f"(v.w) : "memory");
}
template <int CH>
__global__ void scatter_kernel(const float* __restrict__ xin,
                               const int* __restrict__ src,
                               const int* __restrict__ dst) {
    int e = blockIdx.x * 8 + (threadIdx.x >> 5);
    int lane = threadIdx.x & 31;
    if (e >= NEDGES) return;
    int s = src[e], d = dst[e];
    const float* xs = xin + (size_t)s * CH;
    float* od = g_hsum + (size_t)d * CH;
#pragma unroll
    for (int j = 0; j < CH / 128; j++) {
        float4 v = *(const float4*)(xs + j * 128 + lane * 4);
        red_add_v4(od + j * 128 + lane * 4, v);
    }
}

// ---------------- pooling / head ------------------------------------------------
__global__ void pool_kernel() {
    int c = blockIdx.x, d = threadIdx.x;
    const float* p = g_h + (size_t)c * NPC * HID + d;
    float s = 0.f;
#pragma unroll
    for (int j = 0; j < NPC; j++) s += p[j * HID];
    g_cm[c * HID + d] = s * (1.0f / NPC);
}
__global__ void setpool_kernel() {
    int i = blockIdx.x * blockDim.x + threadIdx.x;
    int b = i >> 6, s = i & 63;
    float acc = 0.f;
#pragma unroll
    for (int c = 0; c < CPG; c++) {
        const float* t = g_tt + (size_t)(b * CPG + c) * KWC + s;
        float mx = -3.4e38f;
#pragma unroll
        for (int m = 0; m < MSET; m++) mx = fmaxf(mx, t[m * SDIM]);
        acc += mx;
    }
    g_pool[i] = acc;
}
__global__ void fc1_kernel(const float* __restrict__ w, const float* __restrict__ b) {
    __shared__ float sw[64 * 32];
    __shared__ float sb[32];
    int tid = threadIdx.x;
    for (int i = tid; i < 64 * 32; i += 256) sw[i] = w[i];
    if (tid < 32) sb[tid] = b[tid];
    __syncthreads();
    int r = blockIdx.x * 256 + tid;
    float acc[32];
#pragma unroll
    for (int o = 0; o < 32; o++) acc[o] = sb[o];
    const float* pr = g_pool + (size_t)r * 64;
    for (int d = 0; d < 64; d++) {
        float p = pr[d];
#pragma unroll
        for (int o = 0; o < 32; o++) acc[o] += p * sw[d * 32 + o];
    }
#pragma unroll
    for (int o = 0; o < 32; o++) g_tfc[r * 32 + o] = acc[o];
}
__global__ void stats_kernel() {
    __shared__ float ss[1024], sq[1024];
    int t = threadIdx.x;
    int col = t & 31, g = t >> 5;
    float s = 0.f, q = 0.f;
    for (int r = g; r < NGRAPH; r += 32) {
        float v = g_tfc[r * 32 + col];
        s += v; q += v * v;
    }
    ss[t] = s; sq[t] = q;
    __syncthreads();
    if (t < 32) {
        float S = 0.f, Q = 0.f;
#pragma unroll
        for (int gg = 0; gg < 32; gg++) { S += ss[gg * 32 + t]; Q += sq[gg * 32 + t]; }
        g_stats[t] = S; g_stats[32 + t] = Q;
    }
}
__global__ void fc2_kernel(const float* __restrict__ bng, const float* __restrict__ bnb,
                           const float* __restrict__ w2, const float* __restrict__ b2,
                           float* __restrict__ out) {
    int r = blockIdx.x * 256 + threadIdx.x;
    const float invB = 1.0f / NGRAPH;
    float l0 = b2[0], l1 = b2[1];
#pragma unroll
    for (int o = 0; o < 32; o++) {
        float mu  = g_stats[o] * invB;
        float var = g_stats[32 + o] * invB - mu * mu;
        float v = (g_tfc[r * 32 + o] - mu) * rsqrtf(var + 1e-5f) * bng[o] + bnb[o];
        v = v > 0.f ? v : 0.01f * v;
        l0 += v * w2[o * 2 + 0];
        l1 += v * w2[o * 2 + 1];
    }
    float m = fmaxf(l0, l1);
    float lse = m + logf(expf(l0 - m) + expf(l1 - m));
    out[r * 2 + 0] = l0 - lse;
    out[r * 2 + 1] = l1 - lse;
}

// ---------------- host launcher --------------------------------------------------
extern "C" void kernel_launch(void* const* d_in, const int* in_sizes, int n_in,
                              void* d_out, int out_size) {
    const float* x    = (const float*)d_in[0];
    const float* w0a  = (const float*)d_in[1];
    const float* b0a  = (const float*)d_in[2];
    const float* w0b  = (const float*)d_in[3];
    const float* b0b  = (const float*)d_in[4];
    const float* wra  = (const float*)d_in[5];
    const float* bra  = (const float*)d_in[6];
    const float* wrb  = (const float*)d_in[7];
    const float* brb  = (const float*)d_in[8];
    const float* Wc   = (const float*)d_in[9];
    const float* fc1w = (const float*)d_in[10];
    const float* fc1b = (const float*)d_in[11];
    const float* bng  = (const float*)d_in[12];
    const float* bnb  = (const float*)d_in[13];
    const float* fc2w = (const float*)d_in[14];
    const float* fc2b = (const float*)d_in[15];
    const int*   ei   = (const int*)d_in[16];
    const int* src = ei;
    const int* dst = ei + NEDGES;
    float* out = (float*)d_out;

    void* p;
    cudaGetSymbolAddress(&p, g_hsum); float* hsum = (float*)p;
    cudaGetSymbolAddress(&p, g_t1);   float* t1   = (float*)p;
    cudaGetSymbolAddress(&p, g_h);    float* h    = (float*)p;
    cudaGetSymbolAddress(&p, g_cm);   float* cm   = (float*)p;
    cudaGetSymbolAddress(&p, g_tt);   float* tt   = (float*)p;
    cudaGetSymbolAddress(&p, g_wt_hi); __nv_bfloat16* wh = (__nv_bfloat16*)p;
    cudaGetSymbolAddress(&p, g_wt_lo); __nv_bfloat16* wl = (__nv_bfloat16*)p;

    cudaFuncSetAttribute((const void*)mma_gemm<0, false>, cudaFuncAttributeMaxDynamicSharedMemorySize, GEMM_SMEM);
    cudaFuncSetAttribute((const void*)mma_gemm<1, false>, cudaFuncAttributeMaxDynamicSharedMemorySize, GEMM_SMEM);
    cudaFuncSetAttribute((const void*)mma_gemm<1, true>,  cudaFuncAttributeMaxDynamicSharedMemorySize, GEMM_SMEM);
    cudaFuncSetAttribute((const void*)mma_gemm<2, false>, cudaFuncAttributeMaxDynamicSharedMemorySize, GEMM_SMEM);

    // ---- weight transpose + split (tiny) ----
    split_transpose<<<(INCH * HID + 255) / 256, 256>>>(w0a, wh + OFF_W0A, wl + OFF_W0A, INCH, HID);
    split_transpose<<<(HID * HID + 255) / 256, 256>>>(w0b, wh + OFF_W0B, wl + OFF_W0B, HID, HID);
    split_transpose<<<(HID * HID + 255) / 256, 256>>>(wra,             wh + OFF_WRA0, wl + OFF_WRA0, HID, HID);
    split_transpose<<<(HID * HID + 255) / 256, 256>>>(wra + HID * HID, wh + OFF_WRA1, wl + OFF_WRA1, HID, HID);
    split_transpose<<<(HID * HID + 255) / 256, 256>>>(wrb,             wh + OFF_WRB0, wl + OFF_WRB0, HID, HID);
    split_transpose<<<(HID * HID + 255) / 256, 256>>>(wrb + HID * HID, wh + OFF_WRB1, wl + OFF_WRB1, HID, HID);
    split_transpose<<<(HID * KWC + 255) / 256, 256>>>(Wc, wh + OFF_WC, wl + OFF_WC, HID, KWC);

    dim3 gBig(HID / 128, NNODES / 64);   // (2, 3200)

    // ---- conv0 (K=128) ----
    copy_f4<<<(NNODES * INCH / 4) / 256, 256>>>((const float4*)x, (float4*)hsum, NNODES * INCH / 4);
    scatter_kernel<INCH><<<NEDGES / 8, 256>>>(x, src, dst);
    mma_gemm<1, false><<<gBig, NTHR, GEMM_SMEM>>>(hsum, wh + OFF_W0A, wl + OFF_W0A, b0a, t1, nullptr, INCH, HID);
    mma_gemm<1, true><<<gBig, NTHR, GEMM_SMEM>>>(t1, wh + OFF_W0B, wl + OFF_W0B, b0b, h, hsum, HID, HID);

    // ---- conv1 ----
    scatter_kernel<HID><<<NEDGES / 8, 256>>>(h, src, dst);
    mma_gemm<1, false><<<gBig, NTHR, GEMM_SMEM>>>(hsum, wh + OFF_WRA0, wl + OFF_WRA0, bra, t1, nullptr, HID, HID);
    mma_gemm<1, true><<<gBig, NTHR, GEMM_SMEM>>>(t1, wh + OFF_WRB0, wl + OFF_WRB0, brb, h, hsum, HID, HID);

    // ---- conv2 (no trailing relu) ----
    scatter_kernel<HID><<<NEDGES / 8, 256>>>(h, src, dst);
    mma_gemm<1, false><<<gBig, NTHR, GEMM_SMEM>>>(hsum, wh + OFF_WRA1, wl + OFF_WRA1, bra + HID, t1, nullptr, HID, HID);
    mma_gemm<0, false><<<gBig, NTHR, GEMM_SMEM>>>(t1, wh + OFF_WRB1, wl + OFF_WRB1, brb + HID, h, nullptr, HID, HID);

    // ---- pooling ----
    pool_kernel<<<NCOMP, HID>>>();

    // ---- set-rep GEMM: leaky(cm @ Wc), M=8192, N=512, K=256 ----
    {
        dim3 grid(KWC / 128, NCOMP / 64);   // (4, 128)
        mma_gemm<2, false><<<grid, NTHR, GEMM_SMEM>>>(cm, wh + OFF_WC, wl + OFF_WC, nullptr, tt, nullptr, HID, KWC);
    }
    setpool_kernel<<<(NGRAPH * SDIM) / 256, 256>>>();

    // ---- head ----
    fc1_kernel<<<NGRAPH / 256, 256>>>(fc1w, fc1b);
    stats_kernel<<<1, 1024>>>();
    fc2_kernel<<<NGRAPH / 256, 256>>>(bng, bnb, fc2w, fc2b, out);
}

// round 11
// speedup vs baseline: 1.2070x; 1.1046x over previous
#include <cuda_runtime.h>
#include <cuda_bf16.h>
#include <cstdint>

// ---------------- fixed problem dimensions ----------------------------------
#define NNODES 204800
#define NEDGES 409600
#define INCH   128
#define HID    256
#define NCOMP  8192
#define NGRAPH 4096
#define NPC    25
#define CPG    2
#define SDIM   64
#define MSET   8
#define KWC    512
#define NBLK   800            // NNODES / 256

// ---------------- scratch ----------------------------------------------------
__device__ float g_hsum[(size_t)NNODES * HID];
__device__ float g_t1  [(size_t)NNODES * HID];
__device__ float g_h   [(size_t)NNODES * HID];
__device__ float g_cm  [NCOMP * HID];
__device__ float g_tt  [NCOMP * KWC];
__device__ float g_pool[NGRAPH * SDIM];
__device__ float g_tfc [NGRAPH * 32];
__device__ float g_stats[64];

// CSR scratch
__device__ int g_deg [NNODES];
__device__ int g_offp[NNODES];   // block-local exclusive scan
__device__ int g_off [NNODES];
__device__ int g_cur [NNODES];
__device__ int g_bsum[1024];
__device__ int g_csrc[NEDGES];

// transposed + hi/lo-split weights, bf16, [N][K] K-major
#define OFF_W0A  0
#define OFF_W0B  32768
#define OFF_WRA0 98304
#define OFF_WRB0 163840
#define OFF_WRA1 229376
#define OFF_WRB1 294912
#define OFF_WC   360448
#define WT_TOTAL 491520
__device__ __nv_bfloat16 g_wt_hi[WT_TOTAL];
__device__ __nv_bfloat16 g_wt_lo[WT_TOTAL];

// ---------------- helpers ------------------------------------------------------
__device__ __forceinline__ uint32_t smem_u32(const void* p) {
    uint32_t a;
    asm("{ .reg .u64 t; cvta.to.shared.u64 t, %1; cvt.u32.u64 %0, t; }" : "=r"(a) : "l"(p));
    return a;
}

#define LDSM_X4(r0, r1, r2, r3, addr)                                          \
    asm volatile("ldmatrix.sync.aligned.m8n8.x4.shared.b16 {%0,%1,%2,%3}, [%4];" \
                 : "=r"(r0), "=r"(r1), "=r"(r2), "=r"(r3) : "r"(addr))

#define MMA_BF16(d, a0, a1, a2, a3, b0, b1)                                    \
    asm volatile("mma.sync.aligned.m16n8k16.row.col.f32.bf16.bf16.f32 "        \
                 "{%0,%1,%2,%3}, {%4,%5,%6,%7}, {%8,%9}, {%0,%1,%2,%3};"       \
                 : "+f"((d)[0]), "+f"((d)[1]), "+f"((d)[2]), "+f"((d)[3])      \
                 : "r"(a0), "r"(a1), "r"(a2), "r"(a3), "r"(b0), "r"(b1))

#define CP_ASYNC_16(saddr, gptr)                                               \
    asm volatile("cp.async.cg.shared.global [%0], [%1], 16;"                   \
                 :: "r"(saddr), "l"(gptr))
#define CP_COMMIT() asm volatile("cp.async.commit_group;" ::: "memory")
#define CP_WAIT0()  asm volatile("cp.async.wait_group 0;" ::: "memory")

// ---------------- weight transpose + hi/lo split ------------------------------
__global__ void split_transpose(const float* __restrict__ w, __nv_bfloat16* __restrict__ hi,
                                __nv_bfloat16* __restrict__ lo, int K, int N) {
    int i = blockIdx.x * 256 + threadIdx.x;
    if (i >= K * N) return;
    int k = i / N, n = i % N;
    float v = w[i];
    __nv_bfloat16 h = __float2bfloat16(v);
    hi[(size_t)n * K + k] = h;
    lo[(size_t)n * K + k] = __float2bfloat16(v - __bfloat162float(h));
}

// ---------------- CSR build -----------------------------------------------------
__global__ void csr_zero() {
    int i = blockIdx.x * 256 + threadIdx.x;
    if (i < NNODES) g_deg[i] = 0;
}
__global__ void csr_count(const int* __restrict__ dst) {
    int e = blockIdx.x * 256 + threadIdx.x;
    if (e < NEDGES) atomicAdd(&g_deg[dst[e]], 1);
}
__global__ void csr_scan1() {
    __shared__ int s[256];
    int i = blockIdx.x * 256 + threadIdx.x;
    int v = g_deg[i];
    s[threadIdx.x] = v;
    __syncthreads();
#pragma unroll
    for (int d = 1; d < 256; d <<= 1) {
        int t = (threadIdx.x >= d) ? s[threadIdx.x - d] : 0;
        __syncthreads();
        s[threadIdx.x] += t;
        __syncthreads();
    }
    g_offp[i] = s[threadIdx.x] - v;
    if (threadIdx.x == 255) g_bsum[blockIdx.x] = s[255];
}
__global__ void csr_scan2() {
    __shared__ int s[1024];
    int t = threadIdx.x;
    int v = (t < NBLK) ? g_bsum[t] : 0;
    s[t] = v;
    __syncthreads();
#pragma unroll
    for (int d = 1; d < 1024; d <<= 1) {
        int u = (t >= d) ? s[t - d] : 0;
        __syncthreads();
        s[t] += u;
        __syncthreads();
    }
    if (t < NBLK) g_bsum[t] = s[t] - v;   // exclusive
}
__global__ void csr_scan3() {
    int i = blockIdx.x * 256 + threadIdx.x;
    if (i >= NNODES) return;
    int o = g_offp[i] + g_bsum[i >> 8];
    g_off[i] = o;
    g_cur[i] = o;
}
__global__ void csr_fill(const int* __restrict__ src, const int* __restrict__ dst) {
    int e = blockIdx.x * 256 + threadIdx.x;
    if (e >= NEDGES) return;
    int pos = atomicAdd(&g_cur[dst[e]], 1);
    g_csrc[pos] = src[e];
}

// ---------------- gather: hsum[i] = x[i] + sum_{e in CSR[i]} x[src_e] ----------
template <int CH>
__global__ void gather_kernel(const float* __restrict__ xin) {
    int node = blockIdx.x * 8 + (threadIdx.x >> 5);
    int lane = threadIdx.x & 31;
    if (node >= NNODES) return;
    int beg = g_off[node];
    int deg = g_deg[node];
    float4 acc[CH / 128];
    const float* xr = xin + (size_t)node * CH;
#pragma unroll
    for (int j = 0; j < CH / 128; j++) acc[j] = *(const float4*)(xr + j * 128 + lane * 4);
    for (int e = beg; e < beg + deg; e++) {
        int s = g_csrc[e];
        const float* xs = xin + (size_t)s * CH;
#pragma unroll
        for (int j = 0; j < CH / 128; j++) {
            float4 v = *(const float4*)(xs + j * 128 + lane * 4);
            acc[j].x += v.x; acc[j].y += v.y; acc[j].z += v.z; acc[j].w += v.w;
        }
    }
    float* op = g_hsum + (size_t)node * CH;
#pragma unroll
    for (int j = 0; j < CH / 128; j++) *(float4*)(op + j * 128 + lane * 4) = acc[j];
}

// ---------------- bf16x3 HMMA GEMM (round-6 config) -----------------------------
// CTA tile 128x128, warp tile 64x32 (8 warps 2x4), K-chunk 32, double buffer.
#define ROWB 80
#define STAGE 40960
#define AHI 0
#define ALO 10240
#define BHI 20480
#define BLO 30720
#define GEMM_SMEM (2 * STAGE)

template <int ACT>   // 0 none, 1 relu, 2 leaky(0.01)
__global__ void __launch_bounds__(256)
mma_gemm(const float* __restrict__ A, const __nv_bfloat16* __restrict__ BtHi,
         const __nv_bfloat16* __restrict__ BtLo, const float* __restrict__ bias,
         float* __restrict__ C, int K, int N) {
    extern __shared__ char smem[];
    const uint32_t sb = smem_u32(smem);
    const int tid = threadIdx.x;
    const int lane = tid & 31, wid = tid >> 5;
    const int wm = wid >> 2, wn = wid & 3;
    const int m0 = blockIdx.y * 128, n0 = blockIdx.x * 128;

    const float* Ab = A + (size_t)m0 * K;
    const __nv_bfloat16* BHp = BtHi + (size_t)n0 * K;
    const __nv_bfloat16* BLp = BtLo + (size_t)n0 * K;

    float acc[4][4][4];
#pragma unroll
    for (int i = 0; i < 4; i++)
#pragma unroll
        for (int j = 0; j < 4; j++)
#pragma unroll
            for (int q = 0; q < 4; q++) acc[i][j][q] = 0.f;

    const uint32_t aOff = (uint32_t)(wm * 64 + (lane & 15)) * ROWB + (lane >> 4) * 16;
    const uint32_t bOff = (uint32_t)(wn * 32 + (lane & 7) + (lane >> 4) * 8) * ROWB +
                          ((lane >> 3) & 1) * 16;

    const int arow = tid >> 3, ac4 = tid & 7;
    const int brow = tid >> 2, bc8 = tid & 3;

    auto loadA = [&](int k0, float4* av) {
#pragma unroll
        for (int i = 0; i < 4; i++)
            av[i] = *(const float4*)(Ab + (size_t)(arow + i * 32) * K + k0 + ac4 * 4);
    };
    auto storeA = [&](int buf, const float4* av) {
        char* sd = smem + buf * STAGE;
#pragma unroll
        for (int i = 0; i < 4; i++) {
            float4 v = av[i];
            __nv_bfloat16 h0 = __float2bfloat16(v.x), h1 = __float2bfloat16(v.y);
            __nv_bfloat16 h2 = __float2bfloat16(v.z), h3 = __float2bfloat16(v.w);
            __nv_bfloat16 l0 = __float2bfloat16(v.x - __bfloat162float(h0));
            __nv_bfloat16 l1 = __float2bfloat16(v.y - __bfloat162float(h1));
            __nv_bfloat16 l2 = __float2bfloat16(v.z - __bfloat162float(h2));
            __nv_bfloat16 l3 = __float2bfloat16(v.w - __bfloat162float(h3));
            union { __nv_bfloat162 b[2]; uint2 u; } uh, ul;
            uh.b[0] = __nv_bfloat162(h0, h1); uh.b[1] = __nv_bfloat162(h2, h3);
            ul.b[0] = __nv_bfloat162(l0, l1); ul.b[1] = __nv_bfloat162(l2, l3);
            int off = (arow + i * 32) * ROWB + ac4 * 8;
            *(uint2*)(sd + AHI + off) = uh.u;
            *(uint2*)(sd + ALO + off) = ul.u;
        }
    };
    auto asyncB = [&](int buf, int k0) {
        uint32_t sd = sb + buf * STAGE;
#pragma unroll
        for (int i = 0; i < 2; i++) {
            int row = brow + i * 64;
            uint32_t so = row * ROWB + bc8 * 16;
            CP_ASYNC_16(sd + BHI + so, BHp + (size_t)row * K + k0 + bc8 * 8);
            CP_ASYNC_16(sd + BLO + so, BLp + (size_t)row * K + k0 + bc8 * 8);
        }
    };

    auto compute = [&](int buf) {
        uint32_t sa = sb + buf * STAGE;
#pragma unroll
        for (int k16 = 0; k16 < 2; k16++) {
            uint32_t kadd = k16 * 32;
            uint32_t bh[8], bl[8];
#pragma unroll
            for (int p = 0; p < 2; p++) {
                LDSM_X4(bh[p * 4 + 0], bh[p * 4 + 1], bh[p * 4 + 2], bh[p * 4 + 3],
                        sa + BHI + bOff + p * (16 * ROWB) + kadd);
                LDSM_X4(bl[p * 4 + 0], bl[p * 4 + 1], bl[p * 4 + 2], bl[p * 4 + 3],
                        sa + BLO + bOff + p * (16 * ROWB) + kadd);
            }
#pragma unroll
            for (int mi = 0; mi < 4; mi++) {
                uint32_t ah0, ah1, ah2, ah3, al0, al1, al2, al3;
                LDSM_X4(ah0, ah1, ah2, ah3, sa + AHI + aOff + mi * (16 * ROWB) + kadd);
                LDSM_X4(al0, al1, al2, al3, sa + ALO + aOff + mi * (16 * ROWB) + kadd);
#pragma unroll
                for (int ni = 0; ni < 4; ni++) {
                    MMA_BF16(acc[mi][ni], ah0, ah1, ah2, ah3, bh[ni * 2], bh[ni * 2 + 1]);
                    MMA_BF16(acc[mi][ni], ah0, ah1, ah2, ah3, bl[ni * 2], bl[ni * 2 + 1]);
                    MMA_BF16(acc[mi][ni], al0, al1, al2, al3, bh[ni * 2], bh[ni * 2 + 1]);
                }
            }
        }
    };

    const int nchunk = K / 32;
    float4 av[4];

    loadA(0, av);
    asyncB(0, 0); CP_COMMIT();
    storeA(0, av);
    CP_WAIT0();
    __syncthreads();

    for (int c = 0; c < nchunk; c++) {
        if (c + 1 < nchunk) {
            loadA((c + 1) * 32, av);
            asyncB((c + 1) & 1, (c + 1) * 32); CP_COMMIT();
        }
        compute(c & 1);
        if (c + 1 < nchunk) {
            CP_WAIT0();
            storeA((c + 1) & 1, av);
        }
        __syncthreads();
    }

    // ---- epilogue ----
#pragma unroll
    for (int ni = 0; ni < 4; ni++) {
        int col = n0 + wn * 32 + ni * 8 + (lane & 3) * 2;
        float b0 = 0.f, b1 = 0.f;
        if (bias) { b0 = __ldg(bias + col); b1 = __ldg(bias + col + 1); }
#pragma unroll
        for (int mi = 0; mi < 4; mi++) {
            int row = m0 + wm * 64 + mi * 16 + (lane >> 2);
            float v0 = acc[mi][ni][0] + b0, v1 = acc[mi][ni][1] + b1;
            float v2 = acc[mi][ni][2] + b0, v3 = acc[mi][ni][3] + b1;
            if (ACT == 1) {
                v0 = fmaxf(v0, 0.f); v1 = fmaxf(v1, 0.f);
                v2 = fmaxf(v2, 0.f); v3 = fmaxf(v3, 0.f);
            } else if (ACT == 2) {
                v0 = v0 > 0.f ? v0 : 0.01f * v0;
                v1 = v1 > 0.f ? v1 : 0.01f * v1;
                v2 = v2 > 0.f ? v2 : 0.01f * v2;
                v3 = v3 > 0.f ? v3 : 0.01f * v3;
            }
            *(float2*)(C + (size_t)row * N + col) = make_float2(v0, v1);
            *(float2*)(C + (size_t)(row + 8) * N + col) = make_float2(v2, v3);
        }
    }
}

// ---------------- pooling / head ------------------------------------------------
__global__ void pool_kernel() {
    int c = blockIdx.x, d = threadIdx.x;
    const float* p = g_h + (size_t)c * NPC * HID + d;
    float s = 0.f;
#pragma unroll
    for (int j = 0; j < NPC; j++) s += p[j * HID];
    g_cm[c * HID + d] = s * (1.0f / NPC);
}
__global__ void setpool_kernel() {
    int i = blockIdx.x * blockDim.x + threadIdx.x;
    int b = i >> 6, s = i & 63;
    float acc = 0.f;
#pragma unroll
    for (int c = 0; c < CPG; c++) {
        const float* t = g_tt + (size_t)(b * CPG + c) * KWC + s;
        float mx = -3.4e38f;
#pragma unroll
        for (int m = 0; m < MSET; m++) mx = fmaxf(mx, t[m * SDIM]);
        acc += mx;
    }
    g_pool[i] = acc;
}
__global__ void fc1_kernel(const float* __restrict__ w, const float* __restrict__ b) {
    __shared__ float sw[64 * 32];
    __shared__ float sb[32];
    int tid = threadIdx.x;
    for (int i = tid; i < 64 * 32; i += 256) sw[i] = w[i];
    if (tid < 32) sb[tid] = b[tid];
    __syncthreads();
    int r = blockIdx.x * 256 + tid;
    float acc[32];
#pragma unroll
    for (int o = 0; o < 32; o++) acc[o] = sb[o];
    const float* pr = g_pool + (size_t)r * 64;
    for (int d = 0; d < 64; d++) {
        float p = pr[d];
#pragma unroll
        for (int o = 0; o < 32; o++) acc[o] += p * sw[d * 32 + o];
    }
#pragma unroll
    for (int o = 0; o < 32; o++) g_tfc[r * 32 + o] = acc[o];
}
__global__ void stats_kernel() {
    __shared__ float ss[1024], sq[1024];
    int t = threadIdx.x;
    int col = t & 31, g = t >> 5;
    float s = 0.f, q = 0.f;
    for (int r = g; r < NGRAPH; r += 32) {
        float v = g_tfc[r * 32 + col];
        s += v; q += v * v;
    }
    ss[t] = s; sq[t] = q;
    __syncthreads();
    if (t < 32) {
        float S = 0.f, Q = 0.f;
#pragma unroll
        for (int gg = 0; gg < 32; gg++) { S += ss[gg * 32 + t]; Q += sq[gg * 32 + t]; }
        g_stats[t] = S; g_stats[32 + t] = Q;
    }
}
__global__ void fc2_kernel(const float* __restrict__ bng, const float* __restrict__ bnb,
                           const float* __restrict__ w2, const float* __restrict__ b2,
                           float* __restrict__ out) {
    int r = blockIdx.x * 256 + threadIdx.x;
    const float invB = 1.0f / NGRAPH;
    float l0 = b2[0], l1 = b2[1];
#pragma unroll
    for (int o = 0; o < 32; o++) {
        float mu  = g_stats[o] * invB;
        float var = g_stats[32 + o] * invB - mu * mu;
        float v = (g_tfc[r * 32 + o] - mu) * rsqrtf(var + 1e-5f) * bng[o] + bnb[o];
        v = v > 0.f ? v : 0.01f * v;
        l0 += v * w2[o * 2 + 0];
        l1 += v * w2[o * 2 + 1];
    }
    float m = fmaxf(l0, l1);
    float lse = m + logf(expf(l0 - m) + expf(l1 - m));
    out[r * 2 + 0] = l0 - lse;
    out[r * 2 + 1] = l1 - lse;
}

// ---------------- host launcher --------------------------------------------------
extern "C" void kernel_launch(void* const* d_in, const int* in_sizes, int n_in,
                              void* d_out, int out_size) {
    const float* x    = (const float*)d_in[0];
    const float* w0a  = (const float*)d_in[1];
    const float* b0a  = (const float*)d_in[2];
    const float* w0b  = (const float*)d_in[3];
    const float* b0b  = (const float*)d_in[4];
    const float* wra  = (const float*)d_in[5];
    const float* bra  = (const float*)d_in[6];
    const float* wrb  = (const float*)d_in[7];
    const float* brb  = (const float*)d_in[8];
    const float* Wc   = (const float*)d_in[9];
    const float* fc1w = (const float*)d_in[10];
    const float* fc1b = (const float*)d_in[11];
    const float* bng  = (const float*)d_in[12];
    const float* bnb  = (const float*)d_in[13];
    const float* fc2w = (const float*)d_in[14];
    const float* fc2b = (const float*)d_in[15];
    const int*   ei   = (const int*)d_in[16];
    const int* src = ei;
    const int* dst = ei + NEDGES;
    float* out = (float*)d_out;

    void* p;
    cudaGetSymbolAddress(&p, g_hsum); float* hsum = (float*)p;
    cudaGetSymbolAddress(&p, g_t1);   float* t1   = (float*)p;
    cudaGetSymbolAddress(&p, g_h);    float* h    = (float*)p;
    cudaGetSymbolAddress(&p, g_cm);   float* cm   = (float*)p;
    cudaGetSymbolAddress(&p, g_tt);   float* tt   = (float*)p;
    cudaGetSymbolAddress(&p, g_wt_hi); __nv_bfloat16* wh = (__nv_bfloat16*)p;
    cudaGetSymbolAddress(&p, g_wt_lo); __nv_bfloat16* wl = (__nv_bfloat16*)p;

    cudaFuncSetAttribute((const void*)mma_gemm<0>, cudaFuncAttributeMaxDynamicSharedMemorySize, GEMM_SMEM);
    cudaFuncSetAttribute((const void*)mma_gemm<1>, cudaFuncAttributeMaxDynamicSharedMemorySize, GEMM_SMEM);
    cudaFuncSetAttribute((const void*)mma_gemm<2>, cudaFuncAttributeMaxDynamicSharedMemorySize, GEMM_SMEM);

    // ---- weight transpose + split (tiny) ----
    split_transpose<<<(INCH * HID + 255) / 256, 256>>>(w0a, wh + OFF_W0A, wl + OFF_W0A, INCH, HID);
    split_transpose<<<(HID * HID + 255) / 256, 256>>>(w0b, wh + OFF_W0B, wl + OFF_W0B, HID, HID);
    split_transpose<<<(HID * HID + 255) / 256, 256>>>(wra,             wh + OFF_WRA0, wl + OFF_WRA0, HID, HID);
    split_transpose<<<(HID * HID + 255) / 256, 256>>>(wra + HID * HID, wh + OFF_WRA1, wl + OFF_WRA1, HID, HID);
    split_transpose<<<(HID * HID + 255) / 256, 256>>>(wrb,             wh + OFF_WRB0, wl + OFF_WRB0, HID, HID);
    split_transpose<<<(HID * HID + 255) / 256, 256>>>(wrb + HID * HID, wh + OFF_WRB1, wl + OFF_WRB1, HID, HID);
    split_transpose<<<(HID * KWC + 255) / 256, 256>>>(Wc, wh + OFF_WC, wl + OFF_WC, HID, KWC);

    // ---- CSR build (deterministic per launch) ----
    csr_zero <<<NBLK, 256>>>();
    csr_count<<<NEDGES / 256, 256>>>(dst);
    csr_scan1<<<NBLK, 256>>>();
    csr_scan2<<<1, 1024>>>();
    csr_scan3<<<NBLK, 256>>>();
    csr_fill <<<NEDGES / 256, 256>>>(src, dst);

    dim3 gBig(HID / 128, NNODES / 128);   // (2, 1600)

    // ---- conv0 (K=128) ----
    gather_kernel<INCH><<<NNODES / 8, 256>>>(x);
    mma_gemm<1><<<gBig, 256, GEMM_SMEM>>>(hsum, wh + OFF_W0A, wl + OFF_W0A, b0a, t1, INCH, HID);
    mma_gemm<1><<<gBig, 256, GEMM_SMEM>>>(t1, wh + OFF_W0B, wl + OFF_W0B, b0b, h, HID, HID);   // + relu

    // ---- conv1 ----
    gather_kernel<HID><<<NNODES / 8, 256>>>(h);
    mma_gemm<1><<<gBig, 256, GEMM_SMEM>>>(hsum, wh + OFF_WRA0, wl + OFF_WRA0, bra, t1, HID, HID);
    mma_gemm<1><<<gBig, 256, GEMM_SMEM>>>(t1, wh + OFF_WRB0, wl + OFF_WRB0, brb, h, HID, HID); // + relu

    // ---- conv2 (no trailing relu) ----
    gather_kernel<HID><<<NNODES / 8, 256>>>(h);
    mma_gemm<1><<<gBig, 256, GEMM_SMEM>>>(hsum, wh + OFF_WRA1, wl + OFF_WRA1, bra + HID, t1, HID, HID);
    mma_gemm<0><<<gBig, 256, GEMM_SMEM>>>(t1, wh + OFF_WRB1, wl + OFF_WRB1, brb + HID, h, HID, HID);

    // ---- pooling ----
    pool_kernel<<<NCOMP, HID>>>();

    // ---- set-rep GEMM: leaky(cm @ Wc), M=8192, N=512, K=256 ----
    {
        dim3 grid(KWC / 128, NCOMP / 128);
        mma_gemm<2><<<grid, 256, GEMM_SMEM>>>(cm, wh + OFF_WC, wl + OFF_WC, nullptr, tt, HID, KWC);
    }
    setpool_kernel<<<(NGRAPH * SDIM) / 256, 256>>>();

    // ---- head ----
    fc1_kernel<<<NGRAPH / 256, 256>>>(fc1w, fc1b);
    stats_kernel<<<1, 1024>>>();
    fc2_kernel<<<NGRAPH / 256, 256>>>(bng, bnb, fc2w, fc2b, out);
}

// round 12
// speedup vs baseline: 1.4273x; 1.1826x over previous
#include <cuda_runtime.h>
#include <cuda_fp16.h>
#include <cstdint>

// ---------------- fixed problem dimensions ----------------------------------
#define NNODES 204800
#define NEDGES 409600
#define INCH   128
#define HID    256
#define NCOMP  8192
#define NGRAPH 4096
#define NPC    25
#define CPG    2
#define SDIM   64
#define MSET   8
#define KWC    512
#define NBLK   800            // NNODES / 256

// ---------------- scratch ----------------------------------------------------
__device__ float g_hsum[(size_t)NNODES * HID];
__device__ float g_t1  [(size_t)NNODES * HID];
__device__ float g_h   [(size_t)NNODES * HID];
__device__ float g_cm  [NCOMP * HID];
__device__ float g_tt  [NCOMP * KWC];
__device__ float g_pool[NGRAPH * SDIM];
__device__ float g_tfc [NGRAPH * 32];
__device__ float g_stats[64];

// CSR scratch
__device__ int g_deg [NNODES];
__device__ int g_offp[NNODES];
__device__ int g_off [NNODES];
__device__ int g_cur [NNODES];
__device__ int g_bsum[1024];
__device__ int g_csrc[NEDGES];

// transposed + hi/lo-split weights, fp16, [N][K] K-major
#define OFF_W0A  0
#define OFF_W0B  32768
#define OFF_WRA0 98304
#define OFF_WRB0 163840
#define OFF_WRA1 229376
#define OFF_WRB1 294912
#define OFF_WC   360448
#define WT_TOTAL 491520
__device__ __half g_wt_hi[WT_TOTAL];
__device__ __half g_wt_lo[WT_TOTAL];

// ---------------- helpers ------------------------------------------------------
__device__ __forceinline__ uint32_t smem_u32(const void* p) {
    uint32_t a;
    asm("{ .reg .u64 t; cvta.to.shared.u64 t, %1; cvt.u32.u64 %0, t; }" : "=r"(a) : "l"(p));
    return a;
}

#define LDSM_X4(r0, r1, r2, r3, addr)                                          \
    asm volatile("ldmatrix.sync.aligned.m8n8.x4.shared.b16 {%0,%1,%2,%3}, [%4];" \
                 : "=r"(r0), "=r"(r1), "=r"(r2), "=r"(r3) : "r"(addr))

#define MMA_F16(d, a0, a1, a2, a3, b0, b1)                                     \
    asm volatile("mma.sync.aligned.m16n8k16.row.col.f32.f16.f16.f32 "          \
                 "{%0,%1,%2,%3}, {%4,%5,%6,%7}, {%8,%9}, {%0,%1,%2,%3};"       \
                 : "+f"((d)[0]), "+f"((d)[1]), "+f"((d)[2]), "+f"((d)[3])      \
                 : "r"(a0), "r"(a1), "r"(a2), "r"(a3), "r"(b0), "r"(b1))

#define CP_ASYNC_16(saddr, gptr)                                               \
    asm volatile("cp.async.cg.shared.global [%0], [%1], 16;"                   \
                 :: "r"(saddr), "l"(gptr))
#define CP_COMMIT() asm volatile("cp.async.commit_group;" ::: "memory")
#define CP_WAIT0()  asm volatile("cp.async.wait_group 0;" ::: "memory")

// ---------------- weight transpose + hi/lo split (fp16) ------------------------
__global__ void split_transpose(const float* __restrict__ w, __half* __restrict__ hi,
                                __half* __restrict__ lo, int K, int N) {
    int i = blockIdx.x * 256 + threadIdx.x;
    if (i >= K * N) return;
    int k = i / N, n = i % N;
    float v = w[i];
    __half h = __float2half(v);
    hi[(size_t)n * K + k] = h;
    lo[(size_t)n * K + k] = __float2half(v - __half2float(h));
}

// ---------------- CSR build -----------------------------------------------------
__global__ void csr_zero() {
    int i = blockIdx.x * 256 + threadIdx.x;
    if (i < NNODES) g_deg[i] = 0;
}
__global__ void csr_count(const int* __restrict__ dst) {
    int e = blockIdx.x * 256 + threadIdx.x;
    if (e < NEDGES) atomicAdd(&g_deg[dst[e]], 1);
}
__global__ void csr_scan1() {
    __shared__ int s[256];
    int i = blockIdx.x * 256 + threadIdx.x;
    int v = g_deg[i];
    s[threadIdx.x] = v;
    __syncthreads();
#pragma unroll
    for (int d = 1; d < 256; d <<= 1) {
        int t = (threadIdx.x >= d) ? s[threadIdx.x - d] : 0;
        __syncthreads();
        s[threadIdx.x] += t;
        __syncthreads();
    }
    g_offp[i] = s[threadIdx.x] - v;
    if (threadIdx.x == 255) g_bsum[blockIdx.x] = s[255];
}
__global__ void csr_scan2() {
    __shared__ int s[1024];
    int t = threadIdx.x;
    int v = (t < NBLK) ? g_bsum[t] : 0;
    s[t] = v;
    __syncthreads();
#pragma unroll
    for (int d = 1; d < 1024; d <<= 1) {
        int u = (t >= d) ? s[t - d] : 0;
        __syncthreads();
        s[t] += u;
        __syncthreads();
    }
    if (t < NBLK) g_bsum[t] = s[t] - v;
}
__global__ void csr_scan3() {
    int i = blockIdx.x * 256 + threadIdx.x;
    if (i >= NNODES) return;
    int o = g_offp[i] + g_bsum[i >> 8];
    g_off[i] = o;
    g_cur[i] = o;
}
__global__ void csr_fill(const int* __restrict__ src, const int* __restrict__ dst) {
    int e = blockIdx.x * 256 + threadIdx.x;
    if (e >= NEDGES) return;
    int pos = atomicAdd(&g_cur[dst[e]], 1);
    g_csrc[pos] = src[e];
}

// ---------------- gather: hsum[i] = x[i] + sum_{e in CSR[i]} x[src_e] ----------
template <int CH>
__global__ void gather_kernel(const float* __restrict__ xin) {
    int node = blockIdx.x * 8 + (threadIdx.x >> 5);
    int lane = threadIdx.x & 31;
    if (node >= NNODES) return;
    int beg = g_off[node];
    int deg = g_deg[node];
    float4 acc[CH / 128];
    const float* xr = xin + (size_t)node * CH;
#pragma unroll
    for (int j = 0; j < CH / 128; j++) acc[j] = *(const float4*)(xr + j * 128 + lane * 4);
    for (int e = beg; e < beg + deg; e++) {
        int s = g_csrc[e];
        const float* xs = xin + (size_t)s * CH;
#pragma unroll
        for (int j = 0; j < CH / 128; j++) {
            float4 v = *(const float4*)(xs + j * 128 + lane * 4);
            acc[j].x += v.x; acc[j].y += v.y; acc[j].z += v.z; acc[j].w += v.w;
        }
    }
    float* op = g_hsum + (size_t)node * CH;
#pragma unroll
    for (int j = 0; j < CH / 128; j++) *(float4*)(op + j * 128 + lane * 4) = acc[j];
}

// ---------------- fp16x2 HMMA GEMM ----------------------------------------------
// CTA tile 128x128, warp tile 64x32 (8 warps 2x4), K-chunk 32, double buffer.
// A: single fp16 (converted in-kernel); B: pre-split fp16 hi/lo via cp.async.
// D = Ah*Bh + Ah*Bl  (2 MMAs per k16)
#define ROWB 80
#define A_BYTES 10240
#define AHI 0
#define BHI 10240
#define BLO 20480
#define STAGE 30720
#define GEMM_SMEM (2 * STAGE)   // 61440

template <int ACT>   // 0 none, 1 relu, 2 leaky(0.01)
__global__ void __launch_bounds__(256)
mma_gemm(const float* __restrict__ A, const __half* __restrict__ BtHi,
         const __half* __restrict__ BtLo, const float* __restrict__ bias,
         float* __restrict__ C, int K, int N) {
    extern __shared__ char smem[];
    const uint32_t sb = smem_u32(smem);
    const int tid = threadIdx.x;
    const int lane = tid & 31, wid = tid >> 5;
    const int wm = wid >> 2, wn = wid & 3;
    const int m0 = blockIdx.y * 128, n0 = blockIdx.x * 128;

    const float* Ab = A + (size_t)m0 * K;
    const __half* BHp = BtHi + (size_t)n0 * K;
    const __half* BLp = BtLo + (size_t)n0 * K;

    float acc[4][4][4];
#pragma unroll
    for (int i = 0; i < 4; i++)
#pragma unroll
        for (int j = 0; j < 4; j++)
#pragma unroll
            for (int q = 0; q < 4; q++) acc[i][j][q] = 0.f;

    const uint32_t aOff = (uint32_t)(wm * 64 + (lane & 15)) * ROWB + (lane >> 4) * 16;
    const uint32_t bOff = (uint32_t)(wn * 32 + (lane & 7) + (lane >> 4) * 8) * ROWB +
                          ((lane >> 3) & 1) * 16;

    const int arow = tid >> 3, ac4 = tid & 7;
    const int brow = tid >> 2, bc8 = tid & 3;

    auto loadA = [&](int k0, float4* av) {
#pragma unroll
        for (int i = 0; i < 4; i++)
            av[i] = *(const float4*)(Ab + (size_t)(arow + i * 32) * K + k0 + ac4 * 4);
    };
    auto storeA = [&](int buf, const float4* av) {
        char* sd = smem + buf * STAGE;
#pragma unroll
        for (int i = 0; i < 4; i++) {
            float4 v = av[i];
            union { __half2 b[2]; uint2 u; } uh;
            uh.b[0] = __floats2half2_rn(v.x, v.y);
            uh.b[1] = __floats2half2_rn(v.z, v.w);
            int off = (arow + i * 32) * ROWB + ac4 * 8;
            *(uint2*)(sd + AHI + off) = uh.u;
        }
    };
    auto asyncB = [&](int buf, int k0) {
        uint32_t sd = sb + buf * STAGE;
#pragma unroll
        for (int i = 0; i < 2; i++) {
            int row = brow + i * 64;
            uint32_t so = row * ROWB + bc8 * 16;
            CP_ASYNC_16(sd + BHI + so, BHp + (size_t)row * K + k0 + bc8 * 8);
            CP_ASYNC_16(sd + BLO + so, BLp + (size_t)row * K + k0 + bc8 * 8);
        }
    };

    auto compute = [&](int buf) {
        uint32_t sa = sb + buf * STAGE;
#pragma unroll
        for (int k16 = 0; k16 < 2; k16++) {
            uint32_t kadd = k16 * 32;
            uint32_t bh[8], bl[8];
#pragma unroll
            for (int p = 0; p < 2; p++) {
                LDSM_X4(bh[p * 4 + 0], bh[p * 4 + 1], bh[p * 4 + 2], bh[p * 4 + 3],
                        sa + BHI + bOff + p * (16 * ROWB) + kadd);
                LDSM_X4(bl[p * 4 + 0], bl[p * 4 + 1], bl[p * 4 + 2], bl[p * 4 + 3],
                        sa + BLO + bOff + p * (16 * ROWB) + kadd);
            }
#pragma unroll
            for (int mi = 0; mi < 4; mi++) {
                uint32_t a0, a1, a2, a3;
                LDSM_X4(a0, a1, a2, a3, sa + AHI + aOff + mi * (16 * ROWB) + kadd);
#pragma unroll
                for (int ni = 0; ni < 4; ni++) {
                    MMA_F16(acc[mi][ni], a0, a1, a2, a3, bh[ni * 2], bh[ni * 2 + 1]);
                    MMA_F16(acc[mi][ni], a0, a1, a2, a3, bl[ni * 2], bl[ni * 2 + 1]);
                }
            }
        }
    };

    const int nchunk = K / 32;
    float4 av[4];

    loadA(0, av);
    asyncB(0, 0); CP_COMMIT();
    storeA(0, av);
    CP_WAIT0();
    __syncthreads();

    for (int c = 0; c < nchunk; c++) {
        if (c + 1 < nchunk) {
            loadA((c + 1) * 32, av);
            asyncB((c + 1) & 1, (c + 1) * 32); CP_COMMIT();
        }
        compute(c & 1);
        if (c + 1 < nchunk) {
            CP_WAIT0();
            storeA((c + 1) & 1, av);
        }
        __syncthreads();
    }

    // ---- epilogue ----
#pragma unroll
    for (int ni = 0; ni < 4; ni++) {
        int col = n0 + wn * 32 + ni * 8 + (lane & 3) * 2;
        float b0 = 0.f, b1 = 0.f;
        if (bias) { b0 = __ldg(bias + col); b1 = __ldg(bias + col + 1); }
#pragma unroll
        for (int mi = 0; mi < 4; mi++) {
            int row = m0 + wm * 64 + mi * 16 + (lane >> 2);
            float v0 = acc[mi][ni][0] + b0, v1 = acc[mi][ni][1] + b1;
            float v2 = acc[mi][ni][2] + b0, v3 = acc[mi][ni][3] + b1;
            if (ACT == 1) {
                v0 = fmaxf(v0, 0.f); v1 = fmaxf(v1, 0.f);
                v2 = fmaxf(v2, 0.f); v3 = fmaxf(v3, 0.f);
            } else if (ACT == 2) {
                v0 = v0 > 0.f ? v0 : 0.01f * v0;
                v1 = v1 > 0.f ? v1 : 0.01f * v1;
                v2 = v2 > 0.f ? v2 : 0.01f * v2;
                v3 = v3 > 0.f ? v3 : 0.01f * v3;
            }
            *(float2*)(C + (size_t)row * N + col) = make_float2(v0, v1);
            *(float2*)(C + (size_t)(row + 8) * N + col) = make_float2(v2, v3);
        }
    }
}

// ---------------- pooling / head ------------------------------------------------
__global__ void pool_kernel() {
    int c = blockIdx.x, d = threadIdx.x;
    const float* p = g_h + (size_t)c * NPC * HID + d;
    float s = 0.f;
#pragma unroll
    for (int j = 0; j < NPC; j++) s += p[j * HID];
    g_cm[c * HID + d] = s * (1.0f / NPC);
}
__global__ void setpool_kernel() {
    int i = blockIdx.x * blockDim.x + threadIdx.x;
    int b = i >> 6, s = i & 63;
    float acc = 0.f;
#pragma unroll
    for (int c = 0; c < CPG; c++) {
        const float* t = g_tt + (size_t)(b * CPG + c) * KWC + s;
        float mx = -3.4e38f;
#pragma unroll
        for (int m = 0; m < MSET; m++) mx = fmaxf(mx, t[m * SDIM]);
        acc += mx;
    }
    g_pool[i] = acc;
}
__global__ void fc1_kernel(const float* __restrict__ w, const float* __restrict__ b) {
    __shared__ float sw[64 * 32];
    __shared__ float sb[32];
    int tid = threadIdx.x;
    for (int i = tid; i < 64 * 32; i += 256) sw[i] = w[i];
    if (tid < 32) sb[tid] = b[tid];
    __syncthreads();
    int r = blockIdx.x * 256 + tid;
    float acc[32];
#pragma unroll
    for (int o = 0; o < 32; o++) acc[o] = sb[o];
    const float* pr = g_pool + (size_t)r * 64;
    for (int d = 0; d < 64; d++) {
        float p = pr[d];
#pragma unroll
        for (int o = 0; o < 32; o++) acc[o] += p * sw[d * 32 + o];
    }
#pragma unroll
    for (int o = 0; o < 32; o++) g_tfc[r * 32 + o] = acc[o];
}
__global__ void stats_kernel() {
    __shared__ float ss[1024], sq[1024];
    int t = threadIdx.x;
    int col = t & 31, g = t >> 5;
    float s = 0.f, q = 0.f;
    for (int r = g; r < NGRAPH; r += 32) {
        float v = g_tfc[r * 32 + col];
        s += v; q += v * v;
    }
    ss[t] = s; sq[t] = q;
    __syncthreads();
    if (t < 32) {
        float S = 0.f, Q = 0.f;
#pragma unroll
        for (int gg = 0; gg < 32; gg++) { S += ss[gg * 32 + t]; Q += sq[gg * 32 + t]; }
        g_stats[t] = S; g_stats[32 + t] = Q;
    }
}
__global__ void fc2_kernel(const float* __restrict__ bng, const float* __restrict__ bnb,
                           const float* __restrict__ w2, const float* __restrict__ b2,
                           float* __restrict__ out) {
    int r = blockIdx.x * 256 + threadIdx.x;
    const float invB = 1.0f / NGRAPH;
    float l0 = b2[0], l1 = b2[1];
#pragma unroll
    for (int o = 0; o < 32; o++) {
        float mu  = g_stats[o] * invB;
        float var = g_stats[32 + o] * invB - mu * mu;
        float v = (g_tfc[r * 32 + o] - mu) * rsqrtf(var + 1e-5f) * bng[o] + bnb[o];
        v = v > 0.f ? v : 0.01f * v;
        l0 += v * w2[o * 2 + 0];
        l1 += v * w2[o * 2 + 1];
    }
    float m = fmaxf(l0, l1);
    float lse = m + logf(expf(l0 - m) + expf(l1 - m));
    out[r * 2 + 0] = l0 - lse;
    out[r * 2 + 1] = l1 - lse;
}

// ---------------- host launcher --------------------------------------------------
extern "C" void kernel_launch(void* const* d_in, const int* in_sizes, int n_in,
                              void* d_out, int out_size) {
    const float* x    = (const float*)d_in[0];
    const float* w0a  = (const float*)d_in[1];
    const float* b0a  = (const float*)d_in[2];
    const float* w0b  = (const float*)d_in[3];
    const float* b0b  = (const float*)d_in[4];
    const float* wra  = (const float*)d_in[5];
    const float* bra  = (const float*)d_in[6];
    const float* wrb  = (const float*)d_in[7];
    const float* brb  = (const float*)d_in[8];
    const float* Wc   = (const float*)d_in[9];
    const float* fc1w = (const float*)d_in[10];
    const float* fc1b = (const float*)d_in[11];
    const float* bng  = (const float*)d_in[12];
    const float* bnb  = (const float*)d_in[13];
    const float* fc2w = (const float*)d_in[14];
    const float* fc2b = (const float*)d_in[15];
    const int*   ei   = (const int*)d_in[16];
    const int* src = ei;
    const int* dst = ei + NEDGES;
    float* out = (float*)d_out;

    void* p;
    cudaGetSymbolAddress(&p, g_hsum); float* hsum = (float*)p;
    cudaGetSymbolAddress(&p, g_t1);   float* t1   = (float*)p;
    cudaGetSymbolAddress(&p, g_h);    float* h    = (float*)p;
    cudaGetSymbolAddress(&p, g_cm);   float* cm   = (float*)p;
    cudaGetSymbolAddress(&p, g_tt);   float* tt   = (float*)p;
    cudaGetSymbolAddress(&p, g_wt_hi); __half* wh = (__half*)p;
    cudaGetSymbolAddress(&p, g_wt_lo); __half* wl = (__half*)p;

    cudaFuncSetAttribute((const void*)mma_gemm<0>, cudaFuncAttributeMaxDynamicSharedMemorySize, GEMM_SMEM);
    cudaFuncSetAttribute((const void*)mma_gemm<1>, cudaFuncAttributeMaxDynamicSharedMemorySize, GEMM_SMEM);
    cudaFuncSetAttribute((const void*)mma_gemm<2>, cudaFuncAttributeMaxDynamicSharedMemorySize, GEMM_SMEM);

    // ---- weight transpose + split (tiny) ----
    split_transpose<<<(INCH * HID + 255) / 256, 256>>>(w0a, wh + OFF_W0A, wl + OFF_W0A, INCH, HID);
    split_transpose<<<(HID * HID + 255) / 256, 256>>>(w0b, wh + OFF_W0B, wl + OFF_W0B, HID, HID);
    split_transpose<<<(HID * HID + 255) / 256, 256>>>(wra,             wh + OFF_WRA0, wl + OFF_WRA0, HID, HID);
    split_transpose<<<(HID * HID + 255) / 256, 256>>>(wra + HID * HID, wh + OFF_WRA1, wl + OFF_WRA1, HID, HID);
    split_transpose<<<(HID * HID + 255) / 256, 256>>>(wrb,             wh + OFF_WRB0, wl + OFF_WRB0, HID, HID);
    split_transpose<<<(HID * HID + 255) / 256, 256>>>(wrb + HID * HID, wh + OFF_WRB1, wl + OFF_WRB1, HID, HID);
    split_transpose<<<(HID * KWC + 255) / 256, 256>>>(Wc, wh + OFF_WC, wl + OFF_WC, HID, KWC);

    // ---- CSR build (deterministic per launch) ----
    csr_zero <<<NBLK, 256>>>();
    csr_count<<<NEDGES / 256, 256>>>(dst);
    csr_scan1<<<NBLK, 256>>>();
    csr_scan2<<<1, 1024>>>();
    csr_scan3<<<NBLK, 256>>>();
    csr_fill <<<NEDGES / 256, 256>>>(src, dst);

    dim3 gBig(HID / 128, NNODES / 128);   // (2, 1600)

    // ---- conv0 (K=128) ----
    gather_kernel<INCH><<<NNODES / 8, 256>>>(x);
    mma_gemm<1><<<gBig, 256, GEMM_SMEM>>>(hsum, wh + OFF_W0A, wl + OFF_W0A, b0a, t1, INCH, HID);
    mma_gemm<1><<<gBig, 256, GEMM_SMEM>>>(t1, wh + OFF_W0B, wl + OFF_W0B, b0b, h, HID, HID);   // + relu

    // ---- conv1 ----
    gather_kernel<HID><<<NNODES / 8, 256>>>(h);
    mma_gemm<1><<<gBig, 256, GEMM_SMEM>>>(hsum, wh + OFF_WRA0, wl + OFF_WRA0, bra, t1, HID, HID);
    mma_gemm<1><<<gBig, 256, GEMM_SMEM>>>(t1, wh + OFF_WRB0, wl + OFF_WRB0, brb, h, HID, HID); // + relu

    // ---- conv2 (no trailing relu) ----
    gather_kernel<HID><<<NNODES / 8, 256>>>(h);
    mma_gemm<1><<<gBig, 256, GEMM_SMEM>>>(hsum, wh + OFF_WRA1, wl + OFF_WRA1, bra + HID, t1, HID, HID);
    mma_gemm<0><<<gBig, 256, GEMM_SMEM>>>(t1, wh + OFF_WRB1, wl + OFF_WRB1, brb + HID, h, HID, HID);

    // ---- pooling ----
    pool_kernel<<<NCOMP, HID>>>();

    // ---- set-rep GEMM: leaky(cm @ Wc), M=8192, N=512, K=256 ----
    {
        dim3 grid(KWC / 128, NCOMP / 128);
        mma_gemm<2><<<grid, 256, GEMM_SMEM>>>(cm, wh + OFF_WC, wl + OFF_WC, nullptr, tt, HID, KWC);
    }
    setpool_kernel<<<(NGRAPH * SDIM) / 256, 256>>>();

    // ---- head ----
    fc1_kernel<<<NGRAPH / 256, 256>>>(fc1w, fc1b);
    stats_kernel<<<1, 1024>>>();
    fc2_kernel<<<NGRAPH / 256, 256>>>(bng, bnb, fc2w, fc2b, out);
}

// round 13
// speedup vs baseline: 1.5370x; 1.0769x over previous
#include <cuda_runtime.h>
#include <cuda_fp16.h>
#include <cstdint>

// ---------------- fixed problem dimensions ----------------------------------
#define NNODES 204800
#define NEDGES 409600
#define INCH   128
#define HID    256
#define NCOMP  8192
#define NGRAPH 4096
#define NPC    25
#define CPG    2
#define SDIM   64
#define MSET   8
#define KWC    512
#define NBLK   800            // NNODES / 256

// ---------------- scratch ----------------------------------------------------
__device__ __half g_hsum[(size_t)NNODES * HID];   // fp16 aggregated input (GEMM A)
__device__ __half g_t1 [(size_t)NNODES * HID];    // fp16 hidden (GEMM A)
__device__ float g_h   [(size_t)NNODES * HID];    // fp32 conv output (gather input)
__device__ __half g_cm [NCOMP * HID];             // fp16 component means
__device__ float g_tt  [NCOMP * KWC];
__device__ float g_pool[NGRAPH * SDIM];
__device__ float g_tfc [NGRAPH * 32];
__device__ float g_stats[64];

// CSR scratch
__device__ int g_deg [NNODES];
__device__ int g_offp[NNODES];
__device__ int g_off [NNODES];
__device__ int g_cur [NNODES];
__device__ int g_bsum[1024];
__device__ int g_csrc[NEDGES];

// transposed + hi/lo-split weights, fp16, [N][K] K-major
#define OFF_W0A  0
#define OFF_W0B  32768
#define OFF_WRA0 98304
#define OFF_WRB0 163840
#define OFF_WRA1 229376
#define OFF_WRB1 294912
#define OFF_WC   360448
#define WT_TOTAL 491520
__device__ __half g_wt_hi[WT_TOTAL];
__device__ __half g_wt_lo[WT_TOTAL];

// ---------------- helpers ------------------------------------------------------
__device__ __forceinline__ uint32_t smem_u32(const void* p) {
    uint32_t a;
    asm("{ .reg .u64 t; cvta.to.shared.u64 t, %1; cvt.u32.u64 %0, t; }" : "=r"(a) : "l"(p));
    return a;
}

#define LDSM_X4(r0, r1, r2, r3, addr)                                          \
    asm volatile("ldmatrix.sync.aligned.m8n8.x4.shared.b16 {%0,%1,%2,%3}, [%4];" \
                 : "=r"(r0), "=r"(r1), "=r"(r2), "=r"(r3) : "r"(addr))

#define MMA_F16(d, a0, a1, a2, a3, b0, b1)                                     \
    asm volatile("mma.sync.aligned.m16n8k16.row.col.f32.f16.f16.f32 "          \
                 "{%0,%1,%2,%3}, {%4,%5,%6,%7}, {%8,%9}, {%0,%1,%2,%3};"       \
                 : "+f"((d)[0]), "+f"((d)[1]), "+f"((d)[2]), "+f"((d)[3])      \
                 : "r"(a0), "r"(a1), "r"(a2), "r"(a3), "r"(b0), "r"(b1))

#define CP_ASYNC_16(saddr, gptr)                                               \
    asm volatile("cp.async.cg.shared.global [%0], [%1], 16;"                   \
                 :: "r"(saddr), "l"(gptr))
#define CP_COMMIT() asm volatile("cp.async.commit_group;" ::: "memory")
#define CP_WAIT0()  asm volatile("cp.async.wait_group 0;" ::: "memory")

// ---------------- weight transpose + hi/lo split (fp16) ------------------------
__global__ void split_transpose(const float* __restrict__ w, __half* __restrict__ hi,
                                __half* __restrict__ lo, int K, int N) {
    int i = blockIdx.x * 256 + threadIdx.x;
    if (i >= K * N) return;
    int k = i / N, n = i % N;
    float v = w[i];
    __half h = __float2half(v);
    hi[(size_t)n * K + k] = h;
    lo[(size_t)n * K + k] = __float2half(v - __half2float(h));
}

// ---------------- CSR build -----------------------------------------------------
__global__ void csr_zero() {
    int i = blockIdx.x * 256 + threadIdx.x;
    if (i < NNODES) g_deg[i] = 0;
}
__global__ void csr_count(const int* __restrict__ dst) {
    int e = blockIdx.x * 256 + threadIdx.x;
    if (e < NEDGES) atomicAdd(&g_deg[dst[e]], 1);
}
__global__ void csr_scan1() {
    __shared__ int s[256];
    int i = blockIdx.x * 256 + threadIdx.x;
    int v = g_deg[i];
    s[threadIdx.x] = v;
    __syncthreads();
#pragma unroll
    for (int d = 1; d < 256; d <<= 1) {
        int t = (threadIdx.x >= d) ? s[threadIdx.x - d] : 0;
        __syncthreads();
        s[threadIdx.x] += t;
        __syncthreads();
    }
    g_offp[i] = s[threadIdx.x] - v;
    if (threadIdx.x == 255) g_bsum[blockIdx.x] = s[255];
}
__global__ void csr_scan2() {
    __shared__ int s[1024];
    int t = threadIdx.x;
    int v = (t < NBLK) ? g_bsum[t] : 0;
    s[t] = v;
    __syncthreads();
#pragma unroll
    for (int d = 1; d < 1024; d <<= 1) {
        int u = (t >= d) ? s[t - d] : 0;
        __syncthreads();
        s[t] += u;
        __syncthreads();
    }
    if (t < NBLK) g_bsum[t] = s[t] - v;
}
__global__ void csr_scan3() {
    int i = blockIdx.x * 256 + threadIdx.x;
    if (i >= NNODES) return;
    int o = g_offp[i] + g_bsum[i >> 8];
    g_off[i] = o;
    g_cur[i] = o;
}
__global__ void csr_fill(const int* __restrict__ src, const int* __restrict__ dst) {
    int e = blockIdx.x * 256 + threadIdx.x;
    if (e >= NEDGES) return;
    int pos = atomicAdd(&g_cur[dst[e]], 1);
    g_csrc[pos] = src[e];
}

// ---------------- gather: hsum[i] = fp16(x[i] + sum_{e} x[src_e]) --------------
template <int CH>
__global__ void gather_kernel(const float* __restrict__ xin) {
    int node = blockIdx.x * 8 + (threadIdx.x >> 5);
    int lane = threadIdx.x & 31;
    if (node >= NNODES) return;
    int beg = g_off[node];
    int deg = g_deg[node];
    float4 acc[CH / 128];
    const float* xr = xin + (size_t)node * CH;
#pragma unroll
    for (int j = 0; j < CH / 128; j++) acc[j] = *(const float4*)(xr + j * 128 + lane * 4);
    for (int e = beg; e < beg + deg; e++) {
        int s = g_csrc[e];
        const float* xs = xin + (size_t)s * CH;
#pragma unroll
        for (int j = 0; j < CH / 128; j++) {
            float4 v = *(const float4*)(xs + j * 128 + lane * 4);
            acc[j].x += v.x; acc[j].y += v.y; acc[j].z += v.z; acc[j].w += v.w;
        }
    }
    __half* op = g_hsum + (size_t)node * CH;
#pragma unroll
    for (int j = 0; j < CH / 128; j++) {
        union { __half2 h[2]; uint2 u; } o;
        o.h[0] = __floats2half2_rn(acc[j].x, acc[j].y);
        o.h[1] = __floats2half2_rn(acc[j].z, acc[j].w);
        *(uint2*)(op + j * 128 + lane * 4) = o.u;
    }
}

// ---------------- fp16x2 HMMA GEMM, all-cp.async --------------------------------
// CTA tile 128x128, warp tile 64x32 (8 warps 2x4), K-chunk 32, double buffer.
// A: fp16 [M,K] (pre-rounded by producer); B: fp16 hi/lo.
// D = A*Bh + A*Bl  (2 MMAs per k16). No in-loop conversion at all.
#define ROWB 80
#define AHI 0
#define BHI 10240
#define BLO 20480
#define STAGE 30720
#define GEMM_SMEM (2 * STAGE)   // 61440 -> 2 CTAs/SM

template <int ACT, bool OUTF16>   // ACT: 0 none, 1 relu, 2 leaky(0.01)
__global__ void __launch_bounds__(256)
mma_gemm(const __half* __restrict__ A, const __half* __restrict__ BtHi,
         const __half* __restrict__ BtLo, const float* __restrict__ bias,
         void* __restrict__ Cout, int K, int N) {
    extern __shared__ char smem[];
    const uint32_t sb = smem_u32(smem);
    const int tid = threadIdx.x;
    const int lane = tid & 31, wid = tid >> 5;
    const int wm = wid >> 2, wn = wid & 3;
    const int m0 = blockIdx.y * 128, n0 = blockIdx.x * 128;

    const __half* Ab = A + (size_t)m0 * K;
    const __half* BHp = BtHi + (size_t)n0 * K;
    const __half* BLp = BtLo + (size_t)n0 * K;

    float acc[4][4][4];
#pragma unroll
    for (int i = 0; i < 4; i++)
#pragma unroll
        for (int j = 0; j < 4; j++)
#pragma unroll
            for (int q = 0; q < 4; q++) acc[i][j][q] = 0.f;

    const uint32_t aOff = (uint32_t)(wm * 64 + (lane & 15)) * ROWB + (lane >> 4) * 16;
    const uint32_t bOff = (uint32_t)(wn * 32 + (lane & 7) + (lane >> 4) * 8) * ROWB +
                          ((lane >> 3) & 1) * 16;

    const int arow = tid >> 2, ac8 = tid & 3;   // A: 2 iters (row += 64), 16B per thread
    const int brow = tid >> 2, bc8 = tid & 3;   // B: 2 iters (row += 64)

    auto asyncAll = [&](int buf, int k0) {
        uint32_t sd = sb + buf * STAGE;
#pragma unroll
        for (int i = 0; i < 2; i++) {
            int row = arow + i * 64;
            uint32_t so = row * ROWB + ac8 * 16;
            CP_ASYNC_16(sd + AHI + so, Ab + (size_t)row * K + k0 + ac8 * 8);
        }
#pragma unroll
        for (int i = 0; i < 2; i++) {
            int row = brow + i * 64;
            uint32_t so = row * ROWB + bc8 * 16;
            CP_ASYNC_16(sd + BHI + so, BHp + (size_t)row * K + k0 + bc8 * 8);
            CP_ASYNC_16(sd + BLO + so, BLp + (size_t)row * K + k0 + bc8 * 8);
        }
    };

    auto compute = [&](int buf) {
        uint32_t sa = sb + buf * STAGE;
#pragma unroll
        for (int k16 = 0; k16 < 2; k16++) {
            uint32_t kadd = k16 * 32;
            uint32_t bh[8], bl[8];
#pragma unroll
            for (int p = 0; p < 2; p++) {
                LDSM_X4(bh[p * 4 + 0], bh[p * 4 + 1], bh[p * 4 + 2], bh[p * 4 + 3],
                        sa + BHI + bOff + p * (16 * ROWB) + kadd);
                LDSM_X4(bl[p * 4 + 0], bl[p * 4 + 1], bl[p * 4 + 2], bl[p * 4 + 3],
                        sa + BLO + bOff + p * (16 * ROWB) + kadd);
            }
#pragma unroll
            for (int mi = 0; mi < 4; mi++) {
                uint32_t a0, a1, a2, a3;
                LDSM_X4(a0, a1, a2, a3, sa + AHI + aOff + mi * (16 * ROWB) + kadd);
#pragma unroll
                for (int ni = 0; ni < 4; ni++) {
                    MMA_F16(acc[mi][ni], a0, a1, a2, a3, bh[ni * 2], bh[ni * 2 + 1]);
                    MMA_F16(acc[mi][ni], a0, a1, a2, a3, bl[ni * 2], bl[ni * 2 + 1]);
                }
            }
        }
    };

    const int nchunk = K / 32;

    asyncAll(0, 0); CP_COMMIT();
    CP_WAIT0();
    __syncthreads();

    for (int c = 0; c < nchunk; c++) {
        if (c + 1 < nchunk) { asyncAll((c + 1) & 1, (c + 1) * 32); CP_COMMIT(); }
        compute(c & 1);
        if (c + 1 < nchunk) CP_WAIT0();
        __syncthreads();
    }

    // ---- epilogue ----
#pragma unroll
    for (int ni = 0; ni < 4; ni++) {
        int col = n0 + wn * 32 + ni * 8 + (lane & 3) * 2;
        float b0 = 0.f, b1 = 0.f;
        if (bias) { b0 = __ldg(bias + col); b1 = __ldg(bias + col + 1); }
#pragma unroll
        for (int mi = 0; mi < 4; mi++) {
            int row = m0 + wm * 64 + mi * 16 + (lane >> 2);
            float v0 = acc[mi][ni][0] + b0, v1 = acc[mi][ni][1] + b1;
            float v2 = acc[mi][ni][2] + b0, v3 = acc[mi][ni][3] + b1;
            if (ACT == 1) {
                v0 = fmaxf(v0, 0.f); v1 = fmaxf(v1, 0.f);
                v2 = fmaxf(v2, 0.f); v3 = fmaxf(v3, 0.f);
            } else if (ACT == 2) {
                v0 = v0 > 0.f ? v0 : 0.01f * v0;
                v1 = v1 > 0.f ? v1 : 0.01f * v1;
                v2 = v2 > 0.f ? v2 : 0.01f * v2;
                v3 = v3 > 0.f ? v3 : 0.01f * v3;
            }
            if (OUTF16) {
                __half* C = (__half*)Cout;
                union { __half2 h; uint32_t u; } p0, p1;
                p0.h = __floats2half2_rn(v0, v1);
                p1.h = __floats2half2_rn(v2, v3);
                *(uint32_t*)(C + (size_t)row * N + col) = p0.u;
                *(uint32_t*)(C + (size_t)(row + 8) * N + col) = p1.u;
            } else {
                float* C = (float*)Cout;
                *(float2*)(C + (size_t)row * N + col) = make_float2(v0, v1);
                *(float2*)(C + (size_t)(row + 8) * N + col) = make_float2(v2, v3);
            }
        }
    }
}

// ---------------- pooling / head ------------------------------------------------
__global__ void pool_kernel() {
    int c = blockIdx.x, d = threadIdx.x;
    const float* p = g_h + (size_t)c * NPC * HID + d;
    float s = 0.f;
#pragma unroll
    for (int j = 0; j < NPC; j++) s += p[j * HID];
    g_cm[c * HID + d] = __float2half(s * (1.0f / NPC));
}
__global__ void setpool_kernel() {
    int i = blockIdx.x * blockDim.x + threadIdx.x;
    int b = i >> 6, s = i & 63;
    float acc = 0.f;
#pragma unroll
    for (int c = 0; c < CPG; c++) {
        const float* t = g_tt + (size_t)(b * CPG + c) * KWC + s;
        float mx = -3.4e38f;
#pragma unroll
        for (int m = 0; m < MSET; m++) mx = fmaxf(mx, t[m * SDIM]);
        acc += mx;
    }
    g_pool[i] = acc;
}
__global__ void fc1_kernel(const float* __restrict__ w, const float* __restrict__ b) {
    __shared__ float sw[64 * 32];
    __shared__ float sb[32];
    int tid = threadIdx.x;
    for (int i = tid; i < 64 * 32; i += 256) sw[i] = w[i];
    if (tid < 32) sb[tid] = b[tid];
    __syncthreads();
    int r = blockIdx.x * 256 + tid;
    float acc[32];
#pragma unroll
    for (int o = 0; o < 32; o++) acc[o] = sb[o];
    const float* pr = g_pool + (size_t)r * 64;
    for (int d = 0; d < 64; d++) {
        float p = pr[d];
#pragma unroll
        for (int o = 0; o < 32; o++) acc[o] += p * sw[d * 32 + o];
    }
#pragma unroll
    for (int o = 0; o < 32; o++) g_tfc[r * 32 + o] = acc[o];
}
__global__ void stats_kernel() {
    __shared__ float ss[1024], sq[1024];
    int t = threadIdx.x;
    int col = t & 31, g = t >> 5;
    float s = 0.f, q = 0.f;
    for (int r = g; r < NGRAPH; r += 32) {
        float v = g_tfc[r * 32 + col];
        s += v; q += v * v;
    }
    ss[t] = s; sq[t] = q;
    __syncthreads();
    if (t < 32) {
        float S = 0.f, Q = 0.f;
#pragma unroll
        for (int gg = 0; gg < 32; gg++) { S += ss[gg * 32 + t]; Q += sq[gg * 32 + t]; }
        g_stats[t] = S; g_stats[32 + t] = Q;
    }
}
__global__ void fc2_kernel(const float* __restrict__ bng, const float* __restrict__ bnb,
                           const float* __restrict__ w2, const float* __restrict__ b2,
                           float* __restrict__ out) {
    int r = blockIdx.x * 256 + threadIdx.x;
    const float invB = 1.0f / NGRAPH;
    float l0 = b2[0], l1 = b2[1];
#pragma unroll
    for (int o = 0; o < 32; o++) {
        float mu  = g_stats[o] * invB;
        float var = g_stats[32 + o] * invB - mu * mu;
        float v = (g_tfc[r * 32 + o] - mu) * rsqrtf(var + 1e-5f) * bng[o] + bnb[o];
        v = v > 0.f ? v : 0.01f * v;
        l0 += v * w2[o * 2 + 0];
        l1 += v * w2[o * 2 + 1];
    }
    float m = fmaxf(l0, l1);
    float lse = m + logf(expf(l0 - m) + expf(l1 - m));
    out[r * 2 + 0] = l0 - lse;
    out[r * 2 + 1] = l1 - lse;
}

// ---------------- host launcher --------------------------------------------------
extern "C" void kernel_launch(void* const* d_in, const int* in_sizes, int n_in,
                              void* d_out, int out_size) {
    const float* x    = (const float*)d_in[0];
    const float* w0a  = (const float*)d_in[1];
    const float* b0a  = (const float*)d_in[2];
    const float* w0b  = (const float*)d_in[3];
    const float* b0b  = (const float*)d_in[4];
    const float* wra  = (const float*)d_in[5];
    const float* bra  = (const float*)d_in[6];
    const float* wrb  = (const float*)d_in[7];
    const float* brb  = (const float*)d_in[8];
    const float* Wc   = (const float*)d_in[9];
    const float* fc1w = (const float*)d_in[10];
    const float* fc1b = (const float*)d_in[11];
    const float* bng  = (const float*)d_in[12];
    const float* bnb  = (const float*)d_in[13];
    const float* fc2w = (const float*)d_in[14];
    const float* fc2b = (const float*)d_in[15];
    const int*   ei   = (const int*)d_in[16];
    const int* src = ei;
    const int* dst = ei + NEDGES;
    float* out = (float*)d_out;

    void* p;
    cudaGetSymbolAddress(&p, g_hsum); __half* hsum = (__half*)p;
    cudaGetSymbolAddress(&p, g_t1);   __half* t1   = (__half*)p;
    cudaGetSymbolAddress(&p, g_h);    float*  h    = (float*)p;
    cudaGetSymbolAddress(&p, g_cm);   __half* cm   = (__half*)p;
    cudaGetSymbolAddress(&p, g_tt);   float*  tt   = (float*)p;
    cudaGetSymbolAddress(&p, g_wt_hi); __half* wh = (__half*)p;
    cudaGetSymbolAddress(&p, g_wt_lo); __half* wl = (__half*)p;

    cudaFuncSetAttribute((const void*)mma_gemm<0, false>, cudaFuncAttributeMaxDynamicSharedMemorySize, GEMM_SMEM);
    cudaFuncSetAttribute((const void*)mma_gemm<1, false>, cudaFuncAttributeMaxDynamicSharedMemorySize, GEMM_SMEM);
    cudaFuncSetAttribute((const void*)mma_gemm<1, true>,  cudaFuncAttributeMaxDynamicSharedMemorySize, GEMM_SMEM);
    cudaFuncSetAttribute((const void*)mma_gemm<2, false>, cudaFuncAttributeMaxDynamicSharedMemorySize, GEMM_SMEM);

    // ---- weight transpose + split (tiny) ----
    split_transpose<<<(INCH * HID + 255) / 256, 256>>>(w0a, wh + OFF_W0A, wl + OFF_W0A, INCH, HID);
    split_transpose<<<(HID * HID + 255) / 256, 256>>>(w0b, wh + OFF_W0B, wl + OFF_W0B, HID, HID);
    split_transpose<<<(HID * HID + 255) / 256, 256>>>(wra,             wh + OFF_WRA0, wl + OFF_WRA0, HID, HID);
    split_transpose<<<(HID * HID + 255) / 256, 256>>>(wra + HID * HID, wh + OFF_WRA1, wl + OFF_WRA1, HID, HID);
    split_transpose<<<(HID * HID + 255) / 256, 256>>>(wrb,             wh + OFF_WRB0, wl + OFF_WRB0, HID, HID);
    split_transpose<<<(HID * HID + 255) / 256, 256>>>(wrb + HID * HID, wh + OFF_WRB1, wl + OFF_WRB1, HID, HID);
    split_transpose<<<(HID * KWC + 255) / 256, 256>>>(Wc, wh + OFF_WC, wl + OFF_WC, HID, KWC);

    // ---- CSR build (deterministic per launch) ----
    csr_zero <<<NBLK, 256>>>();
    csr_count<<<NEDGES / 256, 256>>>(dst);
    csr_scan1<<<NBLK, 256>>>();
    csr_scan2<<<1, 1024>>>();
    csr_scan3<<<NBLK, 256>>>();
    csr_fill <<<NEDGES / 256, 256>>>(src, dst);

    dim3 gBig(HID / 128, NNODES / 128);   // (2, 1600)

    // ---- conv0 (K=128) ----
    gather_kernel<INCH><<<NNODES / 8, 256>>>(x);
    mma_gemm<1, true ><<<gBig, 256, GEMM_SMEM>>>(hsum, wh + OFF_W0A, wl + OFF_W0A, b0a, t1, INCH, HID);
    mma_gemm<1, false><<<gBig, 256, GEMM_SMEM>>>(t1, wh + OFF_W0B, wl + OFF_W0B, b0b, h, HID, HID);   // + relu

    // ---- conv1 ----
    gather_kernel<HID><<<NNODES / 8, 256>>>(h);
    mma_gemm<1, true ><<<gBig, 256, GEMM_SMEM>>>(hsum, wh + OFF_WRA0, wl + OFF_WRA0, bra, t1, HID, HID);
    mma_gemm<1, false><<<gBig, 256, GEMM_SMEM>>>(t1, wh + OFF_WRB0, wl + OFF_WRB0, brb, h, HID, HID); // + relu

    // ---- conv2 (no trailing relu) ----
    gather_kernel<HID><<<NNODES / 8, 256>>>(h);
    mma_gemm<1, true ><<<gBig, 256, GEMM_SMEM>>>(hsum, wh + OFF_WRA1, wl + OFF_WRA1, bra + HID, t1, HID, HID);
    mma_gemm<0, false><<<gBig, 256, GEMM_SMEM>>>(t1, wh + OFF_WRB1, wl + OFF_WRB1, brb + HID, h, HID, HID);

    // ---- pooling (emits fp16 component means) ----
    pool_kernel<<<NCOMP, HID>>>();

    // ---- set-rep GEMM: leaky(cm @ Wc), M=8192, N=512, K=256 ----
    {
        dim3 grid(KWC / 128, NCOMP / 128);
        mma_gemm<2, false><<<grid, 256, GEMM_SMEM>>>(cm, wh + OFF_WC, wl + OFF_WC, nullptr, tt, HID, KWC);
    }
    setpool_kernel<<<(NGRAPH * SDIM) / 256, 256>>>();

    // ---- head ----
    fc1_kernel<<<NGRAPH / 256, 256>>>(fc1w, fc1b);
    stats_kernel<<<1, 1024>>>();
    fc2_kernel<<<NGRAPH / 256, 256>>>(bng, bnb, fc2w, fc2b, out);
}

// round 14
// speedup vs baseline: 1.6544x; 1.0764x over previous
#include <cuda_runtime.h>
#include <cuda_fp16.h>
#include <cstdint>

// ---------------- fixed problem dimensions ----------------------------------
#define NNODES 204800
#define NEDGES 409600
#define INCH   128
#define HID    256
#define NCOMP  8192
#define NGRAPH 4096
#define NPC    25
#define CPG    2
#define SDIM   64
#define MSET   8
#define KWC    512
#define NBLK   800            // NNODES / 256

// ---------------- scratch ----------------------------------------------------
__device__ __half g_hsum[(size_t)NNODES * HID];   // fp16 aggregated input (GEMM A)
__device__ __half g_t1 [(size_t)NNODES * HID];    // fp16 hidden (GEMM A)
__device__ __half g_h  [(size_t)NNODES * HID];    // fp16 conv output (gather/pool input)
__device__ __half g_cm [NCOMP * HID];             // fp16 component means
__device__ float g_tt  [NCOMP * KWC];
__device__ float g_pool[NGRAPH * SDIM];
__device__ float g_tfc [NGRAPH * 32];
__device__ float g_stats[64];

// CSR scratch
__device__ int g_deg [NNODES];
__device__ int g_offp[NNODES];
__device__ int g_off [NNODES];
__device__ int g_cur [NNODES];
__device__ int g_bsum[1024];
__device__ int g_csrc[NEDGES];

// transposed + hi/lo-split weights, fp16, [N][K] K-major
#define OFF_W0A  0
#define OFF_W0B  32768
#define OFF_WRA0 98304
#define OFF_WRB0 163840
#define OFF_WRA1 229376
#define OFF_WRB1 294912
#define OFF_WC   360448
#define WT_TOTAL 491520
__device__ __half g_wt_hi[WT_TOTAL];
__device__ __half g_wt_lo[WT_TOTAL];

// ---------------- helpers ------------------------------------------------------
__device__ __forceinline__ uint32_t smem_u32(const void* p) {
    uint32_t a;
    asm("{ .reg .u64 t; cvta.to.shared.u64 t, %1; cvt.u32.u64 %0, t; }" : "=r"(a) : "l"(p));
    return a;
}

#define LDSM_X4(r0, r1, r2, r3, addr)                                          \
    asm volatile("ldmatrix.sync.aligned.m8n8.x4.shared.b16 {%0,%1,%2,%3}, [%4];" \
                 : "=r"(r0), "=r"(r1), "=r"(r2), "=r"(r3) : "r"(addr))

#define MMA_F16(d, a0, a1, a2, a3, b0, b1)                                     \
    asm volatile("mma.sync.aligned.m16n8k16.row.col.f32.f16.f16.f32 "          \
                 "{%0,%1,%2,%3}, {%4,%5,%6,%7}, {%8,%9}, {%0,%1,%2,%3};"       \
                 : "+f"((d)[0]), "+f"((d)[1]), "+f"((d)[2]), "+f"((d)[3])      \
                 : "r"(a0), "r"(a1), "r"(a2), "r"(a3), "r"(b0), "r"(b1))

#define CP_ASYNC_16(saddr, gptr)                                               \
    asm volatile("cp.async.cg.shared.global [%0], [%1], 16;"                   \
                 :: "r"(saddr), "l"(gptr))
#define CP_COMMIT() asm volatile("cp.async.commit_group;" ::: "memory")
#define CP_WAIT0()  asm volatile("cp.async.wait_group 0;" ::: "memory")

// ---------------- weight transpose + hi/lo split (fp16) ------------------------
__global__ void split_transpose(const float* __restrict__ w, __half* __restrict__ hi,
                                __half* __restrict__ lo, int K, int N) {
    int i = blockIdx.x * 256 + threadIdx.x;
    if (i >= K * N) return;
    int k = i / N, n = i % N;
    float v = w[i];
    __half h = __float2half(v);
    hi[(size_t)n * K + k] = h;
    lo[(size_t)n * K + k] = __float2half(v - __half2float(h));
}

// ---------------- CSR build -----------------------------------------------------
__global__ void csr_zero() {
    int i = blockIdx.x * 256 + threadIdx.x;
    if (i < NNODES) g_deg[i] = 0;
}
__global__ void csr_count(const int* __restrict__ dst) {
    int e = blockIdx.x * 256 + threadIdx.x;
    if (e < NEDGES) atomicAdd(&g_deg[dst[e]], 1);
}
__global__ void csr_scan1() {
    __shared__ int s[256];
    int i = blockIdx.x * 256 + threadIdx.x;
    int v = g_deg[i];
    s[threadIdx.x] = v;
    __syncthreads();
#pragma unroll
    for (int d = 1; d < 256; d <<= 1) {
        int t = (threadIdx.x >= d) ? s[threadIdx.x - d] : 0;
        __syncthreads();
        s[threadIdx.x] += t;
        __syncthreads();
    }
    g_offp[i] = s[threadIdx.x] - v;
    if (threadIdx.x == 255) g_bsum[blockIdx.x] = s[255];
}
__global__ void csr_scan2() {
    __shared__ int s[1024];
    int t = threadIdx.x;
    int v = (t < NBLK) ? g_bsum[t] : 0;
    s[t] = v;
    __syncthreads();
#pragma unroll
    for (int d = 1; d < 1024; d <<= 1) {
        int u = (t >= d) ? s[t - d] : 0;
        __syncthreads();
        s[t] += u;
        __syncthreads();
    }
    if (t < NBLK) g_bsum[t] = s[t] - v;
}
__global__ void csr_scan3() {
    int i = blockIdx.x * 256 + threadIdx.x;
    if (i >= NNODES) return;
    int o = g_offp[i] + g_bsum[i >> 8];
    g_off[i] = o;
    g_cur[i] = o;
}
__global__ void csr_fill(const int* __restrict__ src, const int* __restrict__ dst) {
    int e = blockIdx.x * 256 + threadIdx.x;
    if (e >= NEDGES) return;
    int pos = atomicAdd(&g_cur[dst[e]], 1);
    g_csrc[pos] = src[e];
}

// ---------------- gather (fp32 input, conv0): hsum = fp16(x + sum nbr) ---------
template <int CH>
__global__ void gather_f32(const float* __restrict__ xin) {
    int node = blockIdx.x * 8 + (threadIdx.x >> 5);
    int lane = threadIdx.x & 31;
    if (node >= NNODES) return;
    int beg = g_off[node];
    int deg = g_deg[node];
    float4 acc[CH / 128];
    const float* xr = xin + (size_t)node * CH;
#pragma unroll
    for (int j = 0; j < CH / 128; j++) acc[j] = *(const float4*)(xr + j * 128 + lane * 4);
    for (int e = beg; e < beg + deg; e++) {
        int s = g_csrc[e];
        const float* xs = xin + (size_t)s * CH;
#pragma unroll
        for (int j = 0; j < CH / 128; j++) {
            float4 v = *(const float4*)(xs + j * 128 + lane * 4);
            acc[j].x += v.x; acc[j].y += v.y; acc[j].z += v.z; acc[j].w += v.w;
        }
    }
    __half* op = g_hsum + (size_t)node * CH;
#pragma unroll
    for (int j = 0; j < CH / 128; j++) {
        union { __half2 h[2]; uint2 u; } o;
        o.h[0] = __floats2half2_rn(acc[j].x, acc[j].y);
        o.h[1] = __floats2half2_rn(acc[j].z, acc[j].w);
        *(uint2*)(op + j * 128 + lane * 4) = o.u;
    }
}

// ---------------- gather (fp16 input, conv1/2): hsum = fp16(h + sum nbr) -------
template <int CH>
__global__ void gather_f16(const __half* __restrict__ xin) {
    int node = blockIdx.x * 8 + (threadIdx.x >> 5);
    int lane = threadIdx.x & 31;
    if (node >= NNODES) return;
    int beg = g_off[node];
    int deg = g_deg[node];
    float acc[CH / 128][4];
    const __half* xr = xin + (size_t)node * CH;
#pragma unroll
    for (int j = 0; j < CH / 128; j++) {
        union { uint2 u; __half2 h[2]; } v;
        v.u = *(const uint2*)(xr + j * 128 + lane * 4);
        float2 a = __half22float2(v.h[0]), b = __half22float2(v.h[1]);
        acc[j][0] = a.x; acc[j][1] = a.y; acc[j][2] = b.x; acc[j][3] = b.y;
    }
    for (int e = beg; e < beg + deg; e++) {
        int s = g_csrc[e];
        const __half* xs = xin + (size_t)s * CH;
#pragma unroll
        for (int j = 0; j < CH / 128; j++) {
            union { uint2 u; __half2 h[2]; } v;
            v.u = *(const uint2*)(xs + j * 128 + lane * 4);
            float2 a = __half22float2(v.h[0]), b = __half22float2(v.h[1]);
            acc[j][0] += a.x; acc[j][1] += a.y; acc[j][2] += b.x; acc[j][3] += b.y;
        }
    }
    __half* op = g_hsum + (size_t)node * CH;
#pragma unroll
    for (int j = 0; j < CH / 128; j++) {
        union { __half2 h[2]; uint2 u; } o;
        o.h[0] = __floats2half2_rn(acc[j][0], acc[j][1]);
        o.h[1] = __floats2half2_rn(acc[j][2], acc[j][3]);
        *(uint2*)(op + j * 128 + lane * 4) = o.u;
    }
}

// ---------------- fp16x2 HMMA GEMM, all-cp.async --------------------------------
// CTA tile 128x128, warp tile 64x32 (8 warps 2x4), K-chunk 32, double buffer.
#define ROWB 80
#define AHI 0
#define BHI 10240
#define BLO 20480
#define STAGE 30720
#define GEMM_SMEM (2 * STAGE)   // 61440 -> 2 CTAs/SM

template <int ACT, bool OUTF16>   // ACT: 0 none, 1 relu, 2 leaky(0.01)
__global__ void __launch_bounds__(256)
mma_gemm(const __half* __restrict__ A, const __half* __restrict__ BtHi,
         const __half* __restrict__ BtLo, const float* __restrict__ bias,
         void* __restrict__ Cout, int K, int N) {
    extern __shared__ char smem[];
    const uint32_t sb = smem_u32(smem);
    const int tid = threadIdx.x;
    const int lane = tid & 31, wid = tid >> 5;
    const int wm = wid >> 2, wn = wid & 3;
    const int m0 = blockIdx.y * 128, n0 = blockIdx.x * 128;

    const __half* Ab = A + (size_t)m0 * K;
    const __half* BHp = BtHi + (size_t)n0 * K;
    const __half* BLp = BtLo + (size_t)n0 * K;

    float acc[4][4][4];
#pragma unroll
    for (int i = 0; i < 4; i++)
#pragma unroll
        for (int j = 0; j < 4; j++)
#pragma unroll
            for (int q = 0; q < 4; q++) acc[i][j][q] = 0.f;

    const uint32_t aOff = (uint32_t)(wm * 64 + (lane & 15)) * ROWB + (lane >> 4) * 16;
    const uint32_t bOff = (uint32_t)(wn * 32 + (lane & 7) + (lane >> 4) * 8) * ROWB +
                          ((lane >> 3) & 1) * 16;

    const int arow = tid >> 2, ac8 = tid & 3;
    const int brow = tid >> 2, bc8 = tid & 3;

    auto asyncAll = [&](int buf, int k0) {
        uint32_t sd = sb + buf * STAGE;
#pragma unroll
        for (int i = 0; i < 2; i++) {
            int row = arow + i * 64;
            uint32_t so = row * ROWB + ac8 * 16;
            CP_ASYNC_16(sd + AHI + so, Ab + (size_t)row * K + k0 + ac8 * 8);
        }
#pragma unroll
        for (int i = 0; i < 2; i++) {
            int row = brow + i * 64;
            uint32_t so = row * ROWB + bc8 * 16;
            CP_ASYNC_16(sd + BHI + so, BHp + (size_t)row * K + k0 + bc8 * 8);
            CP_ASYNC_16(sd + BLO + so, BLp + (size_t)row * K + k0 + bc8 * 8);
        }
    };

    auto compute = [&](int buf) {
        uint32_t sa = sb + buf * STAGE;
#pragma unroll
        for (int k16 = 0; k16 < 2; k16++) {
            uint32_t kadd = k16 * 32;
            uint32_t bh[8], bl[8];
#pragma unroll
            for (int p = 0; p < 2; p++) {
                LDSM_X4(bh[p * 4 + 0], bh[p * 4 + 1], bh[p * 4 + 2], bh[p * 4 + 3],
                        sa + BHI + bOff + p * (16 * ROWB) + kadd);
                LDSM_X4(bl[p * 4 + 0], bl[p * 4 + 1], bl[p * 4 + 2], bl[p * 4 + 3],
                        sa + BLO + bOff + p * (16 * ROWB) + kadd);
            }
#pragma unroll
            for (int mi = 0; mi < 4; mi++) {
                uint32_t a0, a1, a2, a3;
                LDSM_X4(a0, a1, a2, a3, sa + AHI + aOff + mi * (16 * ROWB) + kadd);
#pragma unroll
                for (int ni = 0; ni < 4; ni++) {
                    MMA_F16(acc[mi][ni], a0, a1, a2, a3, bh[ni * 2], bh[ni * 2 + 1]);
                    MMA_F16(acc[mi][ni], a0, a1, a2, a3, bl[ni * 2], bl[ni * 2 + 1]);
                }
            }
        }
    };

    const int nchunk = K / 32;

    asyncAll(0, 0); CP_COMMIT();
    CP_WAIT0();
    __syncthreads();

    for (int c = 0; c < nchunk; c++) {
        if (c + 1 < nchunk) { asyncAll((c + 1) & 1, (c + 1) * 32); CP_COMMIT(); }
        compute(c & 1);
        if (c + 1 < nchunk) CP_WAIT0();
        __syncthreads();
    }

    // ---- epilogue ----
#pragma unroll
    for (int ni = 0; ni < 4; ni++) {
        int col = n0 + wn * 32 + ni * 8 + (lane & 3) * 2;
        float b0 = 0.f, b1 = 0.f;
        if (bias) { b0 = __ldg(bias + col); b1 = __ldg(bias + col + 1); }
#pragma unroll
        for (int mi = 0; mi < 4; mi++) {
            int row = m0 + wm * 64 + mi * 16 + (lane >> 2);
            float v0 = acc[mi][ni][0] + b0, v1 = acc[mi][ni][1] + b1;
            float v2 = acc[mi][ni][2] + b0, v3 = acc[mi][ni][3] + b1;
            if (ACT == 1) {
                v0 = fmaxf(v0, 0.f); v1 = fmaxf(v1, 0.f);
                v2 = fmaxf(v2, 0.f); v3 = fmaxf(v3, 0.f);
            } else if (ACT == 2) {
                v0 = v0 > 0.f ? v0 : 0.01f * v0;
                v1 = v1 > 0.f ? v1 : 0.01f * v1;
                v2 = v2 > 0.f ? v2 : 0.01f * v2;
                v3 = v3 > 0.f ? v3 : 0.01f * v3;
            }
            if (OUTF16) {
                __half* C = (__half*)Cout;
                union { __half2 h; uint32_t u; } p0, p1;
                p0.h = __floats2half2_rn(v0, v1);
                p1.h = __floats2half2_rn(v2, v3);
                *(uint32_t*)(C + (size_t)row * N + col) = p0.u;
                *(uint32_t*)(C + (size_t)(row + 8) * N + col) = p1.u;
            } else {
                float* C = (float*)Cout;
                *(float2*)(C + (size_t)row * N + col) = make_float2(v0, v1);
                *(float2*)(C + (size_t)(row + 8) * N + col) = make_float2(v2, v3);
            }
        }
    }
}

// ---------------- pooling / head ------------------------------------------------
__global__ void pool_kernel() {
    int c = blockIdx.x, d = threadIdx.x;
    const __half* p = g_h + (size_t)c * NPC * HID + d;
    float s = 0.f;
#pragma unroll
    for (int j = 0; j < NPC; j++) s += __half2float(p[j * HID]);
    g_cm[c * HID + d] = __float2half(s * (1.0f / NPC));
}
__global__ void setpool_kernel() {
    int i = blockIdx.x * blockDim.x + threadIdx.x;
    int b = i >> 6, s = i & 63;
    float acc = 0.f;
#pragma unroll
    for (int c = 0; c < CPG; c++) {
        const float* t = g_tt + (size_t)(b * CPG + c) * KWC + s;
        float mx = -3.4e38f;
#pragma unroll
        for (int m = 0; m < MSET; m++) mx = fmaxf(mx, t[m * SDIM]);
        acc += mx;
    }
    g_pool[i] = acc;
}
__global__ void fc1_kernel(const float* __restrict__ w, const float* __restrict__ b) {
    __shared__ float sw[64 * 32];
    __shared__ float sb[32];
    int tid = threadIdx.x;
    for (int i = tid; i < 64 * 32; i += 256) sw[i] = w[i];
    if (tid < 32) sb[tid] = b[tid];
    __syncthreads();
    int r = blockIdx.x * 256 + tid;
    float acc[32];
#pragma unroll
    for (int o = 0; o < 32; o++) acc[o] = sb[o];
    const float* pr = g_pool + (size_t)r * 64;
    for (int d = 0; d < 64; d++) {
        float p = pr[d];
#pragma unroll
        for (int o = 0; o < 32; o++) acc[o] += p * sw[d * 32 + o];
    }
#pragma unroll
    for (int o = 0; o < 32; o++) g_tfc[r * 32 + o] = acc[o];
}
__global__ void stats_kernel() {
    __shared__ float ss[1024], sq[1024];
    int t = threadIdx.x;
    int col = t & 31, g = t >> 5;
    float s = 0.f, q = 0.f;
    for (int r = g; r < NGRAPH; r += 32) {
        float v = g_tfc[r * 32 + col];
        s += v; q += v * v;
    }
    ss[t] = s; sq[t] = q;
    __syncthreads();
    if (t < 32) {
        float S = 0.f, Q = 0.f;
#pragma unroll
        for (int gg = 0; gg < 32; gg++) { S += ss[gg * 32 + t]; Q += sq[gg * 32 + t]; }
        g_stats[t] = S; g_stats[32 + t] = Q;
    }
}
__global__ void fc2_kernel(const float* __restrict__ bng, const float* __restrict__ bnb,
                           const float* __restrict__ w2, const float* __restrict__ b2,
                           float* __restrict__ out) {
    int r = blockIdx.x * 256 + threadIdx.x;
    const float invB = 1.0f / NGRAPH;
    float l0 = b2[0], l1 = b2[1];
#pragma unroll
    for (int o = 0; o < 32; o++) {
        float mu  = g_stats[o] * invB;
        float var = g_stats[32 + o] * invB - mu * mu;
        float v = (g_tfc[r * 32 + o] - mu) * rsqrtf(var + 1e-5f) * bng[o] + bnb[o];
        v = v > 0.f ? v : 0.01f * v;
        l0 += v * w2[o * 2 + 0];
        l1 += v * w2[o * 2 + 1];
    }
    float m = fmaxf(l0, l1);
    float lse = m + logf(expf(l0 - m) + expf(l1 - m));
    out[r * 2 + 0] = l0 - lse;
    out[r * 2 + 1] = l1 - lse;
}

// ---------------- host launcher --------------------------------------------------
extern "C" void kernel_launch(void* const* d_in, const int* in_sizes, int n_in,
                              void* d_out, int out_size) {
    const float* x    = (const float*)d_in[0];
    const float* w0a  = (const float*)d_in[1];
    const float* b0a  = (const float*)d_in[2];
    const float* w0b  = (const float*)d_in[3];
    const float* b0b  = (const float*)d_in[4];
    const float* wra  = (const float*)d_in[5];
    const float* bra  = (const float*)d_in[6];
    const float* wrb  = (const float*)d_in[7];
    const float* brb  = (const float*)d_in[8];
    const float* Wc   = (const float*)d_in[9];
    const float* fc1w = (const float*)d_in[10];
    const float* fc1b = (const float*)d_in[11];
    const float* bng  = (const float*)d_in[12];
    const float* bnb  = (const float*)d_in[13];
    const float* fc2w = (const float*)d_in[14];
    const float* fc2b = (const float*)d_in[15];
    const int*   ei   = (const int*)d_in[16];
    const int* src = ei;
    const int* dst = ei + NEDGES;
    float* out = (float*)d_out;

    void* p;
    cudaGetSymbolAddress(&p, g_hsum); __half* hsum = (__half*)p;
    cudaGetSymbolAddress(&p, g_t1);   __half* t1   = (__half*)p;
    cudaGetSymbolAddress(&p, g_h);    __half* h    = (__half*)p;
    cudaGetSymbolAddress(&p, g_cm);   __half* cm   = (__half*)p;
    cudaGetSymbolAddress(&p, g_tt);   float*  tt   = (float*)p;
    cudaGetSymbolAddress(&p, g_wt_hi); __half* wh = (__half*)p;
    cudaGetSymbolAddress(&p, g_wt_lo); __half* wl = (__half*)p;

    cudaFuncSetAttribute((const void*)mma_gemm<0, true>,  cudaFuncAttributeMaxDynamicSharedMemorySize, GEMM_SMEM);
    cudaFuncSetAttribute((const void*)mma_gemm<1, true>,  cudaFuncAttributeMaxDynamicSharedMemorySize, GEMM_SMEM);
    cudaFuncSetAttribute((const void*)mma_gemm<2, false>, cudaFuncAttributeMaxDynamicSharedMemorySize, GEMM_SMEM);

    // ---- weight transpose + split (tiny) ----
    split_transpose<<<(INCH * HID + 255) / 256, 256>>>(w0a, wh + OFF_W0A, wl + OFF_W0A, INCH, HID);
    split_transpose<<<(HID * HID + 255) / 256, 256>>>(w0b, wh + OFF_W0B, wl + OFF_W0B, HID, HID);
    split_transpose<<<(HID * HID + 255) / 256, 256>>>(wra,             wh + OFF_WRA0, wl + OFF_WRA0, HID, HID);
    split_transpose<<<(HID * HID + 255) / 256, 256>>>(wra + HID * HID, wh + OFF_WRA1, wl + OFF_WRA1, HID, HID);
    split_transpose<<<(HID * HID + 255) / 256, 256>>>(wrb,             wh + OFF_WRB0, wl + OFF_WRB0, HID, HID);
    split_transpose<<<(HID * HID + 255) / 256, 256>>>(wrb + HID * HID, wh + OFF_WRB1, wl + OFF_WRB1, HID, HID);
    split_transpose<<<(HID * KWC + 255) / 256, 256>>>(Wc, wh + OFF_WC, wl + OFF_WC, HID, KWC);

    // ---- CSR build (deterministic per launch) ----
    csr_zero <<<NBLK, 256>>>();
    csr_count<<<NEDGES / 256, 256>>>(dst);
    csr_scan1<<<NBLK, 256>>>();
    csr_scan2<<<1, 1024>>>();
    csr_scan3<<<NBLK, 256>>>();
    csr_fill <<<NEDGES / 256, 256>>>(src, dst);

    dim3 gBig(HID / 128, NNODES / 128);   // (2, 1600)

    // ---- conv0 (K=128) ----
    gather_f32<INCH><<<NNODES / 8, 256>>>(x);
    mma_gemm<1, true><<<gBig, 256, GEMM_SMEM>>>(hsum, wh + OFF_W0A, wl + OFF_W0A, b0a, t1, INCH, HID);
    mma_gemm<1, true><<<gBig, 256, GEMM_SMEM>>>(t1, wh + OFF_W0B, wl + OFF_W0B, b0b, h, HID, HID);   // + relu

    // ---- conv1 ----
    gather_f16<HID><<<NNODES / 8, 256>>>(h);
    mma_gemm<1, true><<<gBig, 256, GEMM_SMEM>>>(hsum, wh + OFF_WRA0, wl + OFF_WRA0, bra, t1, HID, HID);
    mma_gemm<1, true><<<gBig, 256, GEMM_SMEM>>>(t1, wh + OFF_WRB0, wl + OFF_WRB0, brb, h, HID, HID); // + relu

    // ---- conv2 (no trailing relu) ----
    gather_f16<HID><<<NNODES / 8, 256>>>(h);
    mma_gemm<1, true><<<gBig, 256, GEMM_SMEM>>>(hsum, wh + OFF_WRA1, wl + OFF_WRA1, bra + HID, t1, HID, HID);
    mma_gemm<0, true><<<gBig, 256, GEMM_SMEM>>>(t1, wh + OFF_WRB1, wl + OFF_WRB1, brb + HID, h, HID, HID);

    // ---- pooling (fp16 in, fp16 component means out) ----
    pool_kernel<<<NCOMP, HID>>>();

    // ---- set-rep GEMM: leaky(cm @ Wc), M=8192, N=512, K=256 ----
    {
        dim3 grid(KWC / 128, NCOMP / 128);
        mma_gemm<2, false><<<grid, 256, GEMM_SMEM>>>(cm, wh + OFF_WC, wl + OFF_WC, nullptr, tt, HID, KWC);
    }
    setpool_kernel<<<(NGRAPH * SDIM) / 256, 256>>>();

    // ---- head ----
    fc1_kernel<<<NGRAPH / 256, 256>>>(fc1w, fc1b);
    stats_kernel<<<1, 1024>>>();
    fc2_kernel<<<NGRAPH / 256, 256>>>(bng, bnb, fc2w, fc2b, out);
}

// round 15
// speedup vs baseline: 2.1278x; 1.2861x over previous
#include <cuda_runtime.h>
#include <cuda_fp16.h>
#include <cstdint>

// ---------------- fixed problem dimensions ----------------------------------
#define NNODES 204800
#define NEDGES 409600
#define INCH   128
#define HID    256
#define NCOMP  8192
#define NGRAPH 4096
#define NPC    25
#define CPG    2
#define SDIM   64
#define MSET   8
#define KWC    512
#define NBLK   800            // NNODES / 256

// ---------------- scratch ----------------------------------------------------
__device__ __half g_hsum[(size_t)NNODES * HID];
__device__ __half g_t1 [(size_t)NNODES * HID];
__device__ __half g_h  [(size_t)NNODES * HID];
__device__ __half g_cm [NCOMP * HID];
__device__ float g_tt  [NCOMP * KWC];
__device__ float g_pool[NGRAPH * SDIM];
__device__ float g_tfc [NGRAPH * 32];
__device__ float g_stats[64];

// CSR scratch
__device__ int g_deg [NNODES];
__device__ int g_offp[NNODES];
__device__ int g_off [NNODES];
__device__ int g_cur [NNODES];
__device__ int g_bsum[1024];
__device__ int g_csrc[NEDGES];

// transposed weights, single fp16, [N][K] K-major
#define OFF_W0A  0
#define OFF_W0B  32768
#define OFF_WRA0 98304
#define OFF_WRB0 163840
#define OFF_WRA1 229376
#define OFF_WRB1 294912
#define OFF_WC   360448
#define WT_TOTAL 491520
__device__ __half g_wt[WT_TOTAL];

// ---------------- helpers ------------------------------------------------------
__device__ __forceinline__ uint32_t smem_u32(const void* p) {
    uint32_t a;
    asm("{ .reg .u64 t; cvta.to.shared.u64 t, %1; cvt.u32.u64 %0, t; }" : "=r"(a) : "l"(p));
    return a;
}

#define LDSM_X4(r0, r1, r2, r3, addr)                                          \
    asm volatile("ldmatrix.sync.aligned.m8n8.x4.shared.b16 {%0,%1,%2,%3}, [%4];" \
                 : "=r"(r0), "=r"(r1), "=r"(r2), "=r"(r3) : "r"(addr))

#define MMA_F16(d, a0, a1, a2, a3, b0, b1)                                     \
    asm volatile("mma.sync.aligned.m16n8k16.row.col.f32.f16.f16.f32 "          \
                 "{%0,%1,%2,%3}, {%4,%5,%6,%7}, {%8,%9}, {%0,%1,%2,%3};"       \
                 : "+f"((d)[0]), "+f"((d)[1]), "+f"((d)[2]), "+f"((d)[3])      \
                 : "r"(a0), "r"(a1), "r"(a2), "r"(a3), "r"(b0), "r"(b1))

#define CP_ASYNC_16(saddr, gptr)                                               \
    asm volatile("cp.async.cg.shared.global [%0], [%1], 16;"                   \
                 :: "r"(saddr), "l"(gptr))
#define CP_COMMIT() asm volatile("cp.async.commit_group;" ::: "memory")
#define CP_WAIT0()  asm volatile("cp.async.wait_group 0;" ::: "memory")

// ---------------- weight transpose (fp16, single precision) --------------------
__global__ void transpose_f16(const float* __restrict__ w, __half* __restrict__ o,
                              int K, int N) {
    int i = blockIdx.x * 256 + threadIdx.x;
    if (i >= K * N) return;
    int k = i / N, n = i % N;
    o[(size_t)n * K + k] = __float2half(w[i]);
}

// ---------------- CSR build -----------------------------------------------------
__global__ void csr_zero() {
    int i = blockIdx.x * 256 + threadIdx.x;
    if (i < NNODES) g_deg[i] = 0;
}
__global__ void csr_count(const int* __restrict__ dst) {
    int e = blockIdx.x * 256 + threadIdx.x;
    if (e < NEDGES) atomicAdd(&g_deg[dst[e]], 1);
}
__global__ void csr_scan1() {
    __shared__ int s[256];
    int i = blockIdx.x * 256 + threadIdx.x;
    int v = g_deg[i];
    s[threadIdx.x] = v;
    __syncthreads();
#pragma unroll
    for (int d = 1; d < 256; d <<= 1) {
        int t = (threadIdx.x >= d) ? s[threadIdx.x - d] : 0;
        __syncthreads();
        s[threadIdx.x] += t;
        __syncthreads();
    }
    g_offp[i] = s[threadIdx.x] - v;
    if (threadIdx.x == 255) g_bsum[blockIdx.x] = s[255];
}
__global__ void csr_scan2() {
    __shared__ int s[1024];
    int t = threadIdx.x;
    int v = (t < NBLK) ? g_bsum[t] : 0;
    s[t] = v;
    __syncthreads();
#pragma unroll
    for (int d = 1; d < 1024; d <<= 1) {
        int u = (t >= d) ? s[t - d] : 0;
        __syncthreads();
        s[t] += u;
        __syncthreads();
    }
    if (t < NBLK) g_bsum[t] = s[t] - v;
}
__global__ void csr_scan3() {
    int i = blockIdx.x * 256 + threadIdx.x;
    if (i >= NNODES) return;
    int o = g_offp[i] + g_bsum[i >> 8];
    g_off[i] = o;
    g_cur[i] = o;
}
__global__ void csr_fill(const int* __restrict__ src, const int* __restrict__ dst) {
    int e = blockIdx.x * 256 + threadIdx.x;
    if (e >= NEDGES) return;
    int pos = atomicAdd(&g_cur[dst[e]], 1);
    g_csrc[pos] = src[e];
}

// ---------------- gather (fp32 input, conv0) ------------------------------------
template <int CH>
__global__ void gather_f32(const float* __restrict__ xin) {
    int node = blockIdx.x * 8 + (threadIdx.x >> 5);
    int lane = threadIdx.x & 31;
    if (node >= NNODES) return;
    int beg = g_off[node];
    int deg = g_deg[node];
    float4 acc[CH / 128];
    const float* xr = xin + (size_t)node * CH;
#pragma unroll
    for (int j = 0; j < CH / 128; j++) acc[j] = *(const float4*)(xr + j * 128 + lane * 4);
    for (int e = beg; e < beg + deg; e++) {
        int s = g_csrc[e];
        const float* xs = xin + (size_t)s * CH;
#pragma unroll
        for (int j = 0; j < CH / 128; j++) {
            float4 v = *(const float4*)(xs + j * 128 + lane * 4);
            acc[j].x += v.x; acc[j].y += v.y; acc[j].z += v.z; acc[j].w += v.w;
        }
    }
    __half* op = g_hsum + (size_t)node * CH;
#pragma unroll
    for (int j = 0; j < CH / 128; j++) {
        union { __half2 h[2]; uint2 u; } o;
        o.h[0] = __floats2half2_rn(acc[j].x, acc[j].y);
        o.h[1] = __floats2half2_rn(acc[j].z, acc[j].w);
        *(uint2*)(op + j * 128 + lane * 4) = o.u;
    }
}

// ---------------- gather (fp16 input, conv1/2) ----------------------------------
template <int CH>
__global__ void gather_f16(const __half* __restrict__ xin) {
    int node = blockIdx.x * 8 + (threadIdx.x >> 5);
    int lane = threadIdx.x & 31;
    if (node >= NNODES) return;
    int beg = g_off[node];
    int deg = g_deg[node];
    float acc[CH / 128][4];
    const __half* xr = xin + (size_t)node * CH;
#pragma unroll
    for (int j = 0; j < CH / 128; j++) {
        union { uint2 u; __half2 h[2]; } v;
        v.u = *(const uint2*)(xr + j * 128 + lane * 4);
        float2 a = __half22float2(v.h[0]), b = __half22float2(v.h[1]);
        acc[j][0] = a.x; acc[j][1] = a.y; acc[j][2] = b.x; acc[j][3] = b.y;
    }
    for (int e = beg; e < beg + deg; e++) {
        int s = g_csrc[e];
        const __half* xs = xin + (size_t)s * CH;
#pragma unroll
        for (int j = 0; j < CH / 128; j++) {
            union { uint2 u; __half2 h[2]; } v;
            v.u = *(const uint2*)(xs + j * 128 + lane * 4);
            float2 a = __half22float2(v.h[0]), b = __half22float2(v.h[1]);
            acc[j][0] += a.x; acc[j][1] += a.y; acc[j][2] += b.x; acc[j][3] += b.y;
        }
    }
    __half* op = g_hsum + (size_t)node * CH;
#pragma unroll
    for (int j = 0; j < CH / 128; j++) {
        union { __half2 h[2]; uint2 u; } o;
        o.h[0] = __floats2half2_rn(acc[j][0], acc[j][1]);
        o.h[1] = __floats2half2_rn(acc[j][2], acc[j][3]);
        *(uint2*)(op + j * 128 + lane * 4) = o.u;
    }
}

// ---------------- fp16 HMMA GEMM, all-cp.async, single-precision operands -------
// CTA tile 128x128, warp tile 64x32 (8 warps 2x4), K-chunk 32, double buffer.
// D = A*B  (1 MMA per k16).
#define ROWB 80
#define AHI 0
#define BHI 10240
#define STAGE 20480
#define GEMM_SMEM (2 * STAGE)   // 40960

template <int ACT, bool OUTF16>   // ACT: 0 none, 1 relu, 2 leaky(0.01)
__global__ void __launch_bounds__(256)
mma_gemm(const __half* __restrict__ A, const __half* __restrict__ Bt,
         const float* __restrict__ bias, void* __restrict__ Cout, int K, int N) {
    extern __shared__ char smem[];
    const uint32_t sb = smem_u32(smem);
    const int tid = threadIdx.x;
    const int lane = tid & 31, wid = tid >> 5;
    const int wm = wid >> 2, wn = wid & 3;
    const int m0 = blockIdx.y * 128, n0 = blockIdx.x * 128;

    const __half* Ab = A + (size_t)m0 * K;
    const __half* Bp = Bt + (size_t)n0 * K;

    float acc[4][4][4];
#pragma unroll
    for (int i = 0; i < 4; i++)
#pragma unroll
        for (int j = 0; j < 4; j++)
#pragma unroll
            for (int q = 0; q < 4; q++) acc[i][j][q] = 0.f;

    const uint32_t aOff = (uint32_t)(wm * 64 + (lane & 15)) * ROWB + (lane >> 4) * 16;
    const uint32_t bOff = (uint32_t)(wn * 32 + (lane & 7) + (lane >> 4) * 8) * ROWB +
                          ((lane >> 3) & 1) * 16;

    const int arow = tid >> 2, ac8 = tid & 3;   // 2 iters (row += 64)

    auto asyncAll = [&](int buf, int k0) {
        uint32_t sd = sb + buf * STAGE;
#pragma unroll
        for (int i = 0; i < 2; i++) {
            int row = arow + i * 64;
            uint32_t so = row * ROWB + ac8 * 16;
            CP_ASYNC_16(sd + AHI + so, Ab + (size_t)row * K + k0 + ac8 * 8);
            CP_ASYNC_16(sd + BHI + so, Bp + (size_t)row * K + k0 + ac8 * 8);
        }
    };

    auto compute = [&](int buf) {
        uint32_t sa = sb + buf * STAGE;
#pragma unroll
        for (int k16 = 0; k16 < 2; k16++) {
            uint32_t kadd = k16 * 32;
            uint32_t bh[8];
#pragma unroll
            for (int p = 0; p < 2; p++) {
                LDSM_X4(bh[p * 4 + 0], bh[p * 4 + 1], bh[p * 4 + 2], bh[p * 4 + 3],
                        sa + BHI + bOff + p * (16 * ROWB) + kadd);
            }
#pragma unroll
            for (int mi = 0; mi < 4; mi++) {
                uint32_t a0, a1, a2, a3;
                LDSM_X4(a0, a1, a2, a3, sa + AHI + aOff + mi * (16 * ROWB) + kadd);
#pragma unroll
                for (int ni = 0; ni < 4; ni++) {
                    MMA_F16(acc[mi][ni], a0, a1, a2, a3, bh[ni * 2], bh[ni * 2 + 1]);
                }
            }
        }
    };

    const int nchunk = K / 32;

    asyncAll(0, 0); CP_COMMIT();
    CP_WAIT0();
    __syncthreads();

    for (int c = 0; c < nchunk; c++) {
        if (c + 1 < nchunk) { asyncAll((c + 1) & 1, (c + 1) * 32); CP_COMMIT(); }
        compute(c & 1);
        if (c + 1 < nchunk) CP_WAIT0();
        __syncthreads();
    }

    // ---- epilogue ----
#pragma unroll
    for (int ni = 0; ni < 4; ni++) {
        int col = n0 + wn * 32 + ni * 8 + (lane & 3) * 2;
        float b0 = 0.f, b1 = 0.f;
        if (bias) { b0 = __ldg(bias + col); b1 = __ldg(bias + col + 1); }
#pragma unroll
        for (int mi = 0; mi < 4; mi++) {
            int row = m0 + wm * 64 + mi * 16 + (lane >> 2);
            float v0 = acc[mi][ni][0] + b0, v1 = acc[mi][ni][1] + b1;
            float v2 = acc[mi][ni][2] + b0, v3 = acc[mi][ni][3] + b1;
            if (ACT == 1) {
                v0 = fmaxf(v0, 0.f); v1 = fmaxf(v1, 0.f);
                v2 = fmaxf(v2, 0.f); v3 = fmaxf(v3, 0.f);
            } else if (ACT == 2) {
                v0 = v0 > 0.f ? v0 : 0.01f * v0;
                v1 = v1 > 0.f ? v1 : 0.01f * v1;
                v2 = v2 > 0.f ? v2 : 0.01f * v2;
                v3 = v3 > 0.f ? v3 : 0.01f * v3;
            }
            if (OUTF16) {
                __half* C = (__half*)Cout;
                union { __half2 h; uint32_t u; } p0, p1;
                p0.h = __floats2half2_rn(v0, v1);
                p1.h = __floats2half2_rn(v2, v3);
                *(uint32_t*)(C + (size_t)row * N + col) = p0.u;
                *(uint32_t*)(C + (size_t)(row + 8) * N + col) = p1.u;
            } else {
                float* C = (float*)Cout;
                *(float2*)(C + (size_t)row * N + col) = make_float2(v0, v1);
                *(float2*)(C + (size_t)(row + 8) * N + col) = make_float2(v2, v3);
            }
        }
    }
}

// ---------------- pooling / head ------------------------------------------------
__global__ void pool_kernel() {
    int c = blockIdx.x, d = threadIdx.x;
    const __half* p = g_h + (size_t)c * NPC * HID + d;
    float s = 0.f;
#pragma unroll
    for (int j = 0; j < NPC; j++) s += __half2float(p[j * HID]);
    g_cm[c * HID + d] = __float2half(s * (1.0f / NPC));
}
__global__ void setpool_kernel() {
    int i = blockIdx.x * blockDim.x + threadIdx.x;
    int b = i >> 6, s = i & 63;
    float acc = 0.f;
#pragma unroll
    for (int c = 0; c < CPG; c++) {
        const float* t = g_tt + (size_t)(b * CPG + c) * KWC + s;
        float mx = -3.4e38f;
#pragma unroll
        for (int m = 0; m < MSET; m++) mx = fmaxf(mx, t[m * SDIM]);
        acc += mx;
    }
    g_pool[i] = acc;
}
__global__ void fc1_kernel(const float* __restrict__ w, const float* __restrict__ b) {
    __shared__ float sw[64 * 32];
    __shared__ float sb[32];
    int tid = threadIdx.x;
    for (int i = tid; i < 64 * 32; i += 256) sw[i] = w[i];
    if (tid < 32) sb[tid] = b[tid];
    __syncthreads();
    int r = blockIdx.x * 256 + tid;
    float acc[32];
#pragma unroll
    for (int o = 0; o < 32; o++) acc[o] = sb[o];
    const float* pr = g_pool + (size_t)r * 64;
    for (int d = 0; d < 64; d++) {
        float p = pr[d];
#pragma unroll
        for (int o = 0; o < 32; o++) acc[o] += p * sw[d * 32 + o];
    }
#pragma unroll
    for (int o = 0; o < 32; o++) g_tfc[r * 32 + o] = acc[o];
}
__global__ void stats_kernel() {
    __shared__ float ss[1024], sq[1024];
    int t = threadIdx.x;
    int col = t & 31, g = t >> 5;
    float s = 0.f, q = 0.f;
    for (int r = g; r < NGRAPH; r += 32) {
        float v = g_tfc[r * 32 + col];
        s += v; q += v * v;
    }
    ss[t] = s; sq[t] = q;
    __syncthreads();
    if (t < 32) {
        float S = 0.f, Q = 0.f;
#pragma unroll
        for (int gg = 0; gg < 32; gg++) { S += ss[gg * 32 + t]; Q += sq[gg * 32 + t]; }
        g_stats[t] = S; g_stats[32 + t] = Q;
    }
}
__global__ void fc2_kernel(const float* __restrict__ bng, const float* __restrict__ bnb,
                           const float* __restrict__ w2, const float* __restrict__ b2,
                           float* __restrict__ out) {
    int r = blockIdx.x * 256 + threadIdx.x;
    const float invB = 1.0f / NGRAPH;
    float l0 = b2[0], l1 = b2[1];
#pragma unroll
    for (int o = 0; o < 32; o++) {
        float mu  = g_stats[o] * invB;
        float var = g_stats[32 + o] * invB - mu * mu;
        float v = (g_tfc[r * 32 + o] - mu) * rsqrtf(var + 1e-5f) * bng[o] + bnb[o];
        v = v > 0.f ? v : 0.01f * v;
        l0 += v * w2[o * 2 + 0];
        l1 += v * w2[o * 2 + 1];
    }
    float m = fmaxf(l0, l1);
    float lse = m + logf(expf(l0 - m) + expf(l1 - m));
    out[r * 2 + 0] = l0 - lse;
    out[r * 2 + 1] = l1 - lse;
}

// ---------------- host launcher --------------------------------------------------
extern "C" void kernel_launch(void* const* d_in, const int* in_sizes, int n_in,
                              void* d_out, int out_size) {
    const float* x    = (const float*)d_in[0];
    const float* w0a  = (const float*)d_in[1];
    const float* b0a  = (const float*)d_in[2];
    const float* w0b  = (const float*)d_in[3];
    const float* b0b  = (const float*)d_in[4];
    const float* wra  = (const float*)d_in[5];
    const float* bra  = (const float*)d_in[6];
    const float* wrb  = (const float*)d_in[7];
    const float* brb  = (const float*)d_in[8];
    const float* Wc   = (const float*)d_in[9];
    const float* fc1w = (const float*)d_in[10];
    const float* fc1b = (const float*)d_in[11];
    const float* bng  = (const float*)d_in[12];
    const float* bnb  = (const float*)d_in[13];
    const float* fc2w = (const float*)d_in[14];
    const float* fc2b = (const float*)d_in[15];
    const int*   ei   = (const int*)d_in[16];
    const int* src = ei;
    const int* dst = ei + NEDGES;
    float* out = (float*)d_out;

    void* p;
    cudaGetSymbolAddress(&p, g_hsum); __half* hsum = (__half*)p;
    cudaGetSymbolAddress(&p, g_t1);   __half* t1   = (__half*)p;
    cudaGetSymbolAddress(&p, g_h);    __half* h    = (__half*)p;
    cudaGetSymbolAddress(&p, g_cm);   __half* cm   = (__half*)p;
    cudaGetSymbolAddress(&p, g_tt);   float*  tt   = (float*)p;
    cudaGetSymbolAddress(&p, g_wt);   __half* wt   = (__half*)p;

    cudaFuncSetAttribute((const void*)mma_gemm<0, true>,  cudaFuncAttributeMaxDynamicSharedMemorySize, GEMM_SMEM);
    cudaFuncSetAttribute((const void*)mma_gemm<1, true>,  cudaFuncAttributeMaxDynamicSharedMemorySize, GEMM_SMEM);
    cudaFuncSetAttribute((const void*)mma_gemm<2, false>, cudaFuncAttributeMaxDynamicSharedMemorySize, GEMM_SMEM);

    // ---- weight transpose (tiny) ----
    transpose_f16<<<(INCH * HID + 255) / 256, 256>>>(w0a, wt + OFF_W0A, INCH, HID);
    transpose_f16<<<(HID * HID + 255) / 256, 256>>>(w0b, wt + OFF_W0B, HID, HID);
    transpose_f16<<<(HID * HID + 255) / 256, 256>>>(wra,             wt + OFF_WRA0, HID, HID);
    transpose_f16<<<(HID * HID + 255) / 256, 256>>>(wra + HID * HID, wt + OFF_WRA1, HID, HID);
    transpose_f16<<<(HID * HID + 255) / 256, 256>>>(wrb,             wt + OFF_WRB0, HID, HID);
    transpose_f16<<<(HID * HID + 255) / 256, 256>>>(wrb + HID * HID, wt + OFF_WRB1, HID, HID);
    transpose_f16<<<(HID * KWC + 255) / 256, 256>>>(Wc, wt + OFF_WC, HID, KWC);

    // ---- CSR build (deterministic per launch) ----
    csr_zero <<<NBLK, 256>>>();
    csr_count<<<NEDGES / 256, 256>>>(dst);
    csr_scan1<<<NBLK, 256>>>();
    csr_scan2<<<1, 1024>>>();
    csr_scan3<<<NBLK, 256>>>();
    csr_fill <<<NEDGES / 256, 256>>>(src, dst);

    dim3 gBig(HID / 128, NNODES / 128);   // (2, 1600)

    // ---- conv0 (K=128) ----
    gather_f32<INCH><<<NNODES / 8, 256>>>(x);
    mma_gemm<1, true><<<gBig, 256, GEMM_SMEM>>>(hsum, wt + OFF_W0A, b0a, t1, INCH, HID);
    mma_gemm<1, true><<<gBig, 256, GEMM_SMEM>>>(t1, wt + OFF_W0B, b0b, h, HID, HID);   // + relu

    // ---- conv1 ----
    gather_f16<HID><<<NNODES / 8, 256>>>(h);
    mma_gemm<1, true><<<gBig, 256, GEMM_SMEM>>>(hsum, wt + OFF_WRA0, bra, t1, HID, HID);
    mma_gemm<1, true><<<gBig, 256, GEMM_SMEM>>>(t1, wt + OFF_WRB0, brb, h, HID, HID); // + relu

    // ---- conv2 (no trailing relu) ----
    gather_f16<HID><<<NNODES / 8, 256>>>(h);
    mma_gemm<1, true><<<gBig, 256, GEMM_SMEM>>>(hsum, wt + OFF_WRA1, bra + HID, t1, HID, HID);
    mma_gemm<0, true><<<gBig, 256, GEMM_SMEM>>>(t1, wt + OFF_WRB1, brb + HID, h, HID, HID);

    // ---- pooling ----
    pool_kernel<<<NCOMP, HID>>>();

    // ---- set-rep GEMM: leaky(cm @ Wc), M=8192, N=512, K=256 ----
    {
        dim3 grid(KWC / 128, NCOMP / 128);
        mma_gemm<2, false><<<grid, 256, GEMM_SMEM>>>(cm, wt + OFF_WC, nullptr, tt, HID, KWC);
    }
    setpool_kernel<<<(NGRAPH * SDIM) / 256, 256>>>();

    // ---- head ----
    fc1_kernel<<<NGRAPH / 256, 256>>>(fc1w, fc1b);
    stats_kernel<<<1, 1024>>>();
    fc2_kernel<<<NGRAPH / 256, 256>>>(bng, bnb, fc2w, fc2b, out);
}

// round 16
// speedup vs baseline: 2.2135x; 1.0403x over previous
#include <cuda_runtime.h>
#include <cuda_fp16.h>
#include <cstdint>

// ---------------- fixed problem dimensions ----------------------------------
#define NNODES 204800
#define NEDGES 409600
#define INCH   128
#define HID    256
#define NCOMP  8192
#define NGRAPH 4096
#define NPC    25
#define CPG    2
#define SDIM   64
#define MSET   8
#define KWC    512
#define NBLK   800            // NNODES / 256

// ---------------- scratch ----------------------------------------------------
__device__ __half g_hsum[(size_t)NNODES * HID];
__device__ __half g_t1 [(size_t)NNODES * HID];
__device__ __half g_h  [(size_t)NNODES * HID];
__device__ __half g_cm [NCOMP * HID];
__device__ float g_tt  [NCOMP * KWC];
__device__ float g_pool[NGRAPH * SDIM];
__device__ float g_tfc [NGRAPH * 32];
__device__ float g_stats[64];

// CSR scratch
__device__ int g_deg [NNODES];
__device__ int g_offp[NNODES];
__device__ int g_off [NNODES];
__device__ int g_cur [NNODES];
__device__ int g_bsum[1024];
__device__ int g_csrc[NEDGES];

// transposed weights, single fp16, [N][K] K-major
#define OFF_W0A  0
#define OFF_W0B  32768
#define OFF_WRA0 98304
#define OFF_WRB0 163840
#define OFF_WRA1 229376
#define OFF_WRB1 294912
#define OFF_WC   360448
#define WT_TOTAL 491520
__device__ __half g_wt[WT_TOTAL];

// ---------------- helpers ------------------------------------------------------
__device__ __forceinline__ uint32_t smem_u32(const void* p) {
    uint32_t a;
    asm("{ .reg .u64 t; cvta.to.shared.u64 t, %1; cvt.u32.u64 %0, t; }" : "=r"(a) : "l"(p));
    return a;
}

#define LDSM_X4(r0, r1, r2, r3, addr)                                          \
    asm volatile("ldmatrix.sync.aligned.m8n8.x4.shared.b16 {%0,%1,%2,%3}, [%4];" \
                 : "=r"(r0), "=r"(r1), "=r"(r2), "=r"(r3) : "r"(addr))

#define MMA_F16(d, a0, a1, a2, a3, b0, b1)                                     \
    asm volatile("mma.sync.aligned.m16n8k16.row.col.f32.f16.f16.f32 "          \
                 "{%0,%1,%2,%3}, {%4,%5,%6,%7}, {%8,%9}, {%0,%1,%2,%3};"       \
                 : "+f"((d)[0]), "+f"((d)[1]), "+f"((d)[2]), "+f"((d)[3])      \
                 : "r"(a0), "r"(a1), "r"(a2), "r"(a3), "r"(b0), "r"(b1))

#define CP_ASYNC_16(saddr, gptr)                                               \
    asm volatile("cp.async.cg.shared.global [%0], [%1], 16;"                   \
                 :: "r"(saddr), "l"(gptr))
#define CP_COMMIT()  asm volatile("cp.async.commit_group;" ::: "memory")
#define CP_WAIT0()   asm volatile("cp.async.wait_group 0;" ::: "memory")
#define CP_WAIT1()   asm volatile("cp.async.wait_group 1;" ::: "memory")

// ---------------- merged weight transpose (all 7 weights, one launch) ----------
__global__ void transpose_all(const float* __restrict__ w0a, const float* __restrict__ w0b,
                              const float* __restrict__ wra, const float* __restrict__ wrb,
                              const float* __restrict__ Wc) {
    int i = blockIdx.x * 256 + threadIdx.x;
    if (i >= WT_TOTAL) return;
    const float* srcs[7] = {w0a, w0b, wra, wrb + 0, wra + HID * HID, wrb + HID * HID, Wc};
    // regions sorted by dst offset
    const int dof[8] = {OFF_W0A, OFF_W0B, OFF_WRA0, OFF_WRB0, OFF_WRA1, OFF_WRB1, OFF_WC, WT_TOTAL};
    const int srcIdx[7] = {0, 1, 2, 3, 4, 5, 6};
    const int Ks[7] = {INCH, HID, HID, HID, HID, HID, HID};
    const int Ns[7] = {HID, HID, HID, HID, HID, HID, KWC};
    int r = 0;
#pragma unroll
    for (int q = 1; q < 7; q++) if (i >= dof[q]) r = q;
    int local = i - dof[r];
    int K = Ks[r], N = Ns[r];
    int k = local / N, n = local % N;
    const float* s = srcs[srcIdx[r]];
    g_wt[(size_t)dof[r] + (size_t)n * K + k] = __float2half(s[local]);
}

// ---------------- CSR build -----------------------------------------------------
__global__ void csr_zero() {
    int i = blockIdx.x * 256 + threadIdx.x;
    if (i < NNODES) g_deg[i] = 0;
}
__global__ void csr_count(const int* __restrict__ dst) {
    int e = blockIdx.x * 256 + threadIdx.x;
    if (e < NEDGES) atomicAdd(&g_deg[dst[e]], 1);
}
__global__ void csr_scan1() {
    __shared__ int s[256];
    int i = blockIdx.x * 256 + threadIdx.x;
    int v = g_deg[i];
    s[threadIdx.x] = v;
    __syncthreads();
#pragma unroll
    for (int d = 1; d < 256; d <<= 1) {
        int t = (threadIdx.x >= d) ? s[threadIdx.x - d] : 0;
        __syncthreads();
        s[threadIdx.x] += t;
        __syncthreads();
    }
    g_offp[i] = s[threadIdx.x] - v;
    if (threadIdx.x == 255) g_bsum[blockIdx.x] = s[255];
}
__global__ void csr_scan2() {
    __shared__ int s[1024];
    int t = threadIdx.x;
    int v = (t < NBLK) ? g_bsum[t] : 0;
    s[t] = v;
    __syncthreads();
#pragma unroll
    for (int d = 1; d < 1024; d <<= 1) {
        int u = (t >= d) ? s[t - d] : 0;
        __syncthreads();
        s[t] += u;
        __syncthreads();
    }
    if (t < NBLK) g_bsum[t] = s[t] - v;
}
__global__ void csr_scan3() {
    int i = blockIdx.x * 256 + threadIdx.x;
    if (i >= NNODES) return;
    int o = g_offp[i] + g_bsum[i >> 8];
    g_off[i] = o;
    g_cur[i] = o;
}
__global__ void csr_fill(const int* __restrict__ src, const int* __restrict__ dst) {
    int e = blockIdx.x * 256 + threadIdx.x;
    if (e >= NEDGES) return;
    int pos = atomicAdd(&g_cur[dst[e]], 1);
    g_csrc[pos] = src[e];
}

// ---------------- gather (fp32 input, conv0) ------------------------------------
template <int CH>
__global__ void gather_f32(const float* __restrict__ xin) {
    int node = blockIdx.x * 8 + (threadIdx.x >> 5);
    int lane = threadIdx.x & 31;
    if (node >= NNODES) return;
    int beg = g_off[node];
    int deg = g_deg[node];
    float4 acc[CH / 128];
    const float* xr = xin + (size_t)node * CH;
#pragma unroll
    for (int j = 0; j < CH / 128; j++) acc[j] = *(const float4*)(xr + j * 128 + lane * 4);
    for (int e = beg; e < beg + deg; e++) {
        int s = g_csrc[e];
        const float* xs = xin + (size_t)s * CH;
#pragma unroll
        for (int j = 0; j < CH / 128; j++) {
            float4 v = *(const float4*)(xs + j * 128 + lane * 4);
            acc[j].x += v.x; acc[j].y += v.y; acc[j].z += v.z; acc[j].w += v.w;
        }
    }
    __half* op = g_hsum + (size_t)node * CH;
#pragma unroll
    for (int j = 0; j < CH / 128; j++) {
        union { __half2 h[2]; uint2 u; } o;
        o.h[0] = __floats2half2_rn(acc[j].x, acc[j].y);
        o.h[1] = __floats2half2_rn(acc[j].z, acc[j].w);
        *(uint2*)(op + j * 128 + lane * 4) = o.u;
    }
}

// ---------------- gather (fp16 input, conv1/2) ----------------------------------
template <int CH>
__global__ void gather_f16(const __half* __restrict__ xin) {
    int node = blockIdx.x * 8 + (threadIdx.x >> 5);
    int lane = threadIdx.x & 31;
    if (node >= NNODES) return;
    int beg = g_off[node];
    int deg = g_deg[node];
    float acc[CH / 128][4];
    const __half* xr = xin + (size_t)node * CH;
#pragma unroll
    for (int j = 0; j < CH / 128; j++) {
        union { uint2 u; __half2 h[2]; } v;
        v.u = *(const uint2*)(xr + j * 128 + lane * 4);
        float2 a = __half22float2(v.h[0]), b = __half22float2(v.h[1]);
        acc[j][0] = a.x; acc[j][1] = a.y; acc[j][2] = b.x; acc[j][3] = b.y;
    }
    for (int e = beg; e < beg + deg; e++) {
        int s = g_csrc[e];
        const __half* xs = xin + (size_t)s * CH;
#pragma unroll
        for (int j = 0; j < CH / 128; j++) {
            union { uint2 u; __half2 h[2]; } v;
            v.u = *(const uint2*)(xs + j * 128 + lane * 4);
            float2 a = __half22float2(v.h[0]), b = __half22float2(v.h[1]);
            acc[j][0] += a.x; acc[j][1] += a.y; acc[j][2] += b.x; acc[j][3] += b.y;
        }
    }
    __half* op = g_hsum + (size_t)node * CH;
#pragma unroll
    for (int j = 0; j < CH / 128; j++) {
        union { __half2 h[2]; uint2 u; } o;
        o.h[0] = __floats2half2_rn(acc[j][0], acc[j][1]);
        o.h[1] = __floats2half2_rn(acc[j][2], acc[j][3]);
        *(uint2*)(op + j * 128 + lane * 4) = o.u;
    }
}

// ---------------- fp16 HMMA GEMM, 3-stage cp.async pipeline ---------------------
// CTA tile 128x128, warp tile 64x32 (8 warps 2x4), K-chunk 32, triple buffer.
#define ROWB 80
#define AHI 0
#define BHI 10240
#define STAGE 20480
#define GEMM_SMEM (3 * STAGE)   // 61440 -> 2 CTAs/SM

template <int ACT, bool OUTF16>   // ACT: 0 none, 1 relu, 2 leaky(0.01)
__global__ void __launch_bounds__(256)
mma_gemm(const __half* __restrict__ A, const __half* __restrict__ Bt,
         const float* __restrict__ bias, void* __restrict__ Cout, int K, int N) {
    extern __shared__ char smem[];
    const uint32_t sb = smem_u32(smem);
    const int tid = threadIdx.x;
    const int lane = tid & 31, wid = tid >> 5;
    const int wm = wid >> 2, wn = wid & 3;
    const int m0 = blockIdx.y * 128, n0 = blockIdx.x * 128;

    const __half* Ab = A + (size_t)m0 * K;
    const __half* Bp = Bt + (size_t)n0 * K;

    float acc[4][4][4];
#pragma unroll
    for (int i = 0; i < 4; i++)
#pragma unroll
        for (int j = 0; j < 4; j++)
#pragma unroll
            for (int q = 0; q < 4; q++) acc[i][j][q] = 0.f;

    const uint32_t aOff = (uint32_t)(wm * 64 + (lane & 15)) * ROWB + (lane >> 4) * 16;
    const uint32_t bOff = (uint32_t)(wn * 32 + (lane & 7) + (lane >> 4) * 8) * ROWB +
                          ((lane >> 3) & 1) * 16;

    const int arow = tid >> 2, ac8 = tid & 3;   // 2 iters (row += 64)

    auto asyncAll = [&](int buf, int k0) {
        uint32_t sd = sb + buf * STAGE;
#pragma unroll
        for (int i = 0; i < 2; i++) {
            int row = arow + i * 64;
            uint32_t so = row * ROWB + ac8 * 16;
            CP_ASYNC_16(sd + AHI + so, Ab + (size_t)row * K + k0 + ac8 * 8);
            CP_ASYNC_16(sd + BHI + so, Bp + (size_t)row * K + k0 + ac8 * 8);
        }
    };

    auto compute = [&](int buf) {
        uint32_t sa = sb + buf * STAGE;
#pragma unroll
        for (int k16 = 0; k16 < 2; k16++) {
            uint32_t kadd = k16 * 32;
            uint32_t bh[8];
#pragma unroll
            for (int p = 0; p < 2; p++) {
                LDSM_X4(bh[p * 4 + 0], bh[p * 4 + 1], bh[p * 4 + 2], bh[p * 4 + 3],
                        sa + BHI + bOff + p * (16 * ROWB) + kadd);
            }
#pragma unroll
            for (int mi = 0; mi < 4; mi++) {
                uint32_t a0, a1, a2, a3;
                LDSM_X4(a0, a1, a2, a3, sa + AHI + aOff + mi * (16 * ROWB) + kadd);
#pragma unroll
                for (int ni = 0; ni < 4; ni++) {
                    MMA_F16(acc[mi][ni], a0, a1, a2, a3, bh[ni * 2], bh[ni * 2 + 1]);
                }
            }
        }
    };

    const int nchunk = K / 32;

    // prologue: preload chunks 0 and 1
    asyncAll(0, 0); CP_COMMIT();
    if (nchunk > 1) { asyncAll(1, 32); CP_COMMIT(); CP_WAIT1(); }
    else CP_WAIT0();
    __syncthreads();

    for (int c = 0; c < nchunk; c++) {
        compute(c % 3);
        bool more = (c + 2 < nchunk);
        if (more) { asyncAll((c + 2) % 3, (c + 2) * 32); CP_COMMIT(); }
        if (c + 1 < nchunk) {
            if (more) CP_WAIT1(); else CP_WAIT0();
            __syncthreads();
        }
    }

    // ---- epilogue ----
#pragma unroll
    for (int ni = 0; ni < 4; ni++) {
        int col = n0 + wn * 32 + ni * 8 + (lane & 3) * 2;
        float b0 = 0.f, b1 = 0.f;
        if (bias) { b0 = __ldg(bias + col); b1 = __ldg(bias + col + 1); }
#pragma unroll
        for (int mi = 0; mi < 4; mi++) {
            int row = m0 + wm * 64 + mi * 16 + (lane >> 2);
            float v0 = acc[mi][ni][0] + b0, v1 = acc[mi][ni][1] + b1;
            float v2 = acc[mi][ni][2] + b0, v3 = acc[mi][ni][3] + b1;
            if (ACT == 1) {
                v0 = fmaxf(v0, 0.f); v1 = fmaxf(v1, 0.f);
                v2 = fmaxf(v2, 0.f); v3 = fmaxf(v3, 0.f);
            } else if (ACT == 2) {
                v0 = v0 > 0.f ? v0 : 0.01f * v0;
                v1 = v1 > 0.f ? v1 : 0.01f * v1;
                v2 = v2 > 0.f ? v2 : 0.01f * v2;
                v3 = v3 > 0.f ? v3 : 0.01f * v3;
            }
            if (OUTF16) {
                __half* C = (__half*)Cout;
                union { __half2 h; uint32_t u; } p0, p1;
                p0.h = __floats2half2_rn(v0, v1);
                p1.h = __floats2half2_rn(v2, v3);
                *(uint32_t*)(C + (size_t)row * N + col) = p0.u;
                *(uint32_t*)(C + (size_t)(row + 8) * N + col) = p1.u;
            } else {
                float* C = (float*)Cout;
                *(float2*)(C + (size_t)row * N + col) = make_float2(v0, v1);
                *(float2*)(C + (size_t)(row + 8) * N + col) = make_float2(v2, v3);
            }
        }
    }
}

// ---------------- pooling / head ------------------------------------------------
__global__ void pool_kernel() {
    int c = blockIdx.x, d = threadIdx.x;
    const __half* p = g_h + (size_t)c * NPC * HID + d;
    float s = 0.f;
#pragma unroll
    for (int j = 0; j < NPC; j++) s += __half2float(p[j * HID]);
    g_cm[c * HID + d] = __float2half(s * (1.0f / NPC));
}
__global__ void setpool_kernel() {
    int i = blockIdx.x * blockDim.x + threadIdx.x;
    int b = i >> 6, s = i & 63;
    float acc = 0.f;
#pragma unroll
    for (int c = 0; c < CPG; c++) {
        const float* t = g_tt + (size_t)(b * CPG + c) * KWC + s;
        float mx = -3.4e38f;
#pragma unroll
        for (int m = 0; m < MSET; m++) mx = fmaxf(mx, t[m * SDIM]);
        acc += mx;
    }
    g_pool[i] = acc;
}
__global__ void fc1_kernel(const float* __restrict__ w, const float* __restrict__ b) {
    __shared__ float sw[64 * 32];
    __shared__ float sb[32];
    int tid = threadIdx.x;
    for (int i = tid; i < 64 * 32; i += 256) sw[i] = w[i];
    if (tid < 32) sb[tid] = b[tid];
    __syncthreads();
    int r = blockIdx.x * 256 + tid;
    float acc[32];
#pragma unroll
    for (int o = 0; o < 32; o++) acc[o] = sb[o];
    const float* pr = g_pool + (size_t)r * 64;
    for (int d = 0; d < 64; d++) {
        float p = pr[d];
#pragma unroll
        for (int o = 0; o < 32; o++) acc[o] += p * sw[d * 32 + o];
    }
#pragma unroll
    for (int o = 0; o < 32; o++) g_tfc[r * 32 + o] = acc[o];
}
__global__ void stats_kernel() {
    __shared__ float ss[1024], sq[1024];
    int t = threadIdx.x;
    int col = t & 31, g = t >> 5;
    float s = 0.f, q = 0.f;
    for (int r = g; r < NGRAPH; r += 32) {
        float v = g_tfc[r * 32 + col];
        s += v; q += v * v;
    }
    ss[t] = s; sq[t] = q;
    __syncthreads();
    if (t < 32) {
        float S = 0.f, Q = 0.f;
#pragma unroll
        for (int gg = 0; gg < 32; gg++) { S += ss[gg * 32 + t]; Q += sq[gg * 32 + t]; }
        g_stats[t] = S; g_stats[32 + t] = Q;
    }
}
__global__ void fc2_kernel(const float* __restrict__ bng, const float* __restrict__ bnb,
                           const float* __restrict__ w2, const float* __restrict__ b2,
                           float* __restrict__ out) {
    int r = blockIdx.x * 256 + threadIdx.x;
    const float invB = 1.0f / NGRAPH;
    float l0 = b2[0], l1 = b2[1];
#pragma unroll
    for (int o = 0; o < 32; o++) {
        float mu  = g_stats[o] * invB;
        float var = g_stats[32 + o] * invB - mu * mu;
        float v = (g_tfc[r * 32 + o] - mu) * rsqrtf(var + 1e-5f) * bng[o] + bnb[o];
        v = v > 0.f ? v : 0.01f * v;
        l0 += v * w2[o * 2 + 0];
        l1 += v * w2[o * 2 + 1];
    }
    float m = fmaxf(l0, l1);
    float lse = m + logf(expf(l0 - m) + expf(l1 - m));
    out[r * 2 + 0] = l0 - lse;
    out[r * 2 + 1] = l1 - lse;
}

// ---------------- host launcher --------------------------------------------------
extern "C" void kernel_launch(void* const* d_in, const int* in_sizes, int n_in,
                              void* d_out, int out_size) {
    const float* x    = (const float*)d_in[0];
    const float* w0a  = (const float*)d_in[1];
    const float* b0a  = (const float*)d_in[2];
    const float* w0b  = (const float*)d_in[3];
    const float* b0b  = (const float*)d_in[4];
    const float* wra  = (const float*)d_in[5];
    const float* bra  = (const float*)d_in[6];
    const float* wrb  = (const float*)d_in[7];
    const float* brb  = (const float*)d_in[8];
    const float* Wc   = (const float*)d_in[9];
    const float* fc1w = (const float*)d_in[10];
    const float* fc1b = (const float*)d_in[11];
    const float* bng  = (const float*)d_in[12];
    const float* bnb  = (const float*)d_in[13];
    const float* fc2w = (const float*)d_in[14];
    const float* fc2b = (const float*)d_in[15];
    const int*   ei   = (const int*)d_in[16];
    const int* src = ei;
    const int* dst = ei + NEDGES;
    float* out = (float*)d_out;

    void* p;
    cudaGetSymbolAddress(&p, g_hsum); __half* hsum = (__half*)p;
    cudaGetSymbolAddress(&p, g_t1);   __half* t1   = (__half*)p;
    cudaGetSymbolAddress(&p, g_h);    __half* h    = (__half*)p;
    cudaGetSymbolAddress(&p, g_cm);   __half* cm   = (__half*)p;
    cudaGetSymbolAddress(&p, g_tt);   float*  tt   = (float*)p;
    cudaGetSymbolAddress(&p, g_wt);   __half* wt   = (__half*)p;

    cudaFuncSetAttribute((const void*)mma_gemm<0, true>,  cudaFuncAttributeMaxDynamicSharedMemorySize, GEMM_SMEM);
    cudaFuncSetAttribute((const void*)mma_gemm<1, true>,  cudaFuncAttributeMaxDynamicSharedMemorySize, GEMM_SMEM);
    cudaFuncSetAttribute((const void*)mma_gemm<2, false>, cudaFuncAttributeMaxDynamicSharedMemorySize, GEMM_SMEM);

    // ---- weight transpose (one launch) ----
    transpose_all<<<(WT_TOTAL + 255) / 256, 256>>>(w0a, w0b, wra, wrb, Wc);

    // ---- CSR build (deterministic per launch) ----
    csr_zero <<<NBLK, 256>>>();
    csr_count<<<NEDGES / 256, 256>>>(dst);
    csr_scan1<<<NBLK, 256>>>();
    csr_scan2<<<1, 1024>>>();
    csr_scan3<<<NBLK, 256>>>();
    csr_fill <<<NEDGES / 256, 256>>>(src, dst);

    dim3 gBig(HID / 128, NNODES / 128);   // (2, 1600)

    // ---- conv0 (K=128) ----
    gather_f32<INCH><<<NNODES / 8, 256>>>(x);
    mma_gemm<1, true><<<gBig, 256, GEMM_SMEM>>>(hsum, wt + OFF_W0A, b0a, t1, INCH, HID);
    mma_gemm<1, true><<<gBig, 256, GEMM_SMEM>>>(t1, wt + OFF_W0B, b0b, h, HID, HID);   // + relu

    // ---- conv1 ----
    gather_f16<HID><<<NNODES / 8, 256>>>(h);
    mma_gemm<1, true><<<gBig, 256, GEMM_SMEM>>>(hsum, wt + OFF_WRA0, bra, t1, HID, HID);
    mma_gemm<1, true><<<gBig, 256, GEMM_SMEM>>>(t1, wt + OFF_WRB0, brb, h, HID, HID); // + relu

    // ---- conv2 (no trailing relu) ----
    gather_f16<HID><<<NNODES / 8, 256>>>(h);
    mma_gemm<1, true><<<gBig, 256, GEMM_SMEM>>>(hsum, wt + OFF_WRA1, bra + HID, t1, HID, HID);
    mma_gemm<0, true><<<gBig, 256, GEMM_SMEM>>>(t1, wt + OFF_WRB1, brb + HID, h, HID, HID);

    // ---- pooling ----
    pool_kernel<<<NCOMP, HID>>>();

    // ---- set-rep GEMM: leaky(cm @ Wc), M=8192, N=512, K=256 ----
    {
        dim3 grid(KWC / 128, NCOMP / 128);
        mma_gemm<2, false><<<grid, 256, GEMM_SMEM>>>(cm, wt + OFF_WC, nullptr, tt, HID, KWC);
    }
    setpool_kernel<<<(NGRAPH * SDIM) / 256, 256>>>();

    // ---- head ----
    fc1_kernel<<<NGRAPH / 256, 256>>>(fc1w, fc1b);
    stats_kernel<<<1, 1024>>>();
    fc2_kernel<<<NGRAPH / 256, 256>>>(bng, bnb, fc2w, fc2b, out);
}